// round 15
// baseline (speedup 1.0000x reference)
#include <cuda_runtime.h>
#include <cuda_bf16.h>
#include <cuda_fp16.h>
#include <cstdint>

#define EPS 1e-5f
#define HW 6400
#define NC 128
#define ND 256
#define NH 80
#define SPLIT 8

// ---------------- tensor-core helpers ----------------------------------------
__device__ __forceinline__ void ldsm4(uint32_t& r0, uint32_t& r1,
                                      uint32_t& r2, uint32_t& r3, uint32_t a) {
    asm volatile("ldmatrix.sync.aligned.m8n8.x4.shared.b16 {%0,%1,%2,%3},[%4];"
        : "=r"(r0), "=r"(r1), "=r"(r2), "=r"(r3) : "r"(a));
}
__device__ __forceinline__ void ldsm4t(uint32_t& r0, uint32_t& r1,
                                       uint32_t& r2, uint32_t& r3, uint32_t a) {
    asm volatile("ldmatrix.sync.aligned.m8n8.x4.trans.shared.b16 {%0,%1,%2,%3},[%4];"
        : "=r"(r0), "=r"(r1), "=r"(r2), "=r"(r3) : "r"(a));
}
__device__ __forceinline__ void mma_bf16(float* d, uint32_t a0, uint32_t a1,
                                         uint32_t a2, uint32_t a3,
                                         uint32_t b0, uint32_t b1) {
    asm volatile("mma.sync.aligned.m16n8k16.row.col.f32.bf16.bf16.f32 "
        "{%0,%1,%2,%3},{%4,%5,%6,%7},{%8,%9},{%0,%1,%2,%3};"
        : "+f"(d[0]), "+f"(d[1]), "+f"(d[2]), "+f"(d[3])
        : "r"(a0), "r"(a1), "r"(a2), "r"(a3), "r"(b0), "r"(b1));
}
__device__ __forceinline__ void mma_f16(float* d, uint32_t a0, uint32_t a1,
                                        uint32_t a2, uint32_t a3,
                                        uint32_t b0, uint32_t b1) {
    asm volatile("mma.sync.aligned.m16n8k16.row.col.f32.f16.f16.f32 "
        "{%0,%1,%2,%3},{%4,%5,%6,%7},{%8,%9},{%0,%1,%2,%3};"
        : "+f"(d[0]), "+f"(d[1]), "+f"(d[2]), "+f"(d[3])
        : "r"(a0), "r"(a1), "r"(a2), "r"(a3), "r"(b0), "r"(b1));
}
__device__ __forceinline__ void mma_tf32(float* d, uint32_t a0, uint32_t a1,
                                         uint32_t a2, uint32_t a3,
                                         uint32_t b0, uint32_t b1) {
    asm volatile("mma.sync.aligned.m16n8k8.row.col.f32.tf32.tf32.f32 "
        "{%0,%1,%2,%3},{%4,%5,%6,%7},{%8,%9},{%0,%1,%2,%3};"
        : "+f"(d[0]), "+f"(d[1]), "+f"(d[2]), "+f"(d[3])
        : "r"(a0), "r"(a1), "r"(a2), "r"(a3), "r"(b0), "r"(b1));
}
__device__ __forceinline__ float tf32r(float x) {
    uint32_t r;
    asm("cvt.rna.tf32.f32 %0, %1;" : "=r"(r) : "f"(x));
    return __uint_as_float(r);
}
__device__ __forceinline__ void cpa16(uint32_t s, const void* g) {
    asm volatile("cp.async.cg.shared.global [%0], [%1], 16;" :: "r"(s), "l"(g));
}
#define CPA_COMMIT() asm volatile("cp.async.commit_group;")

// ---------------- scratch (static device globals; no allocation) -------------
__device__ float d_x1 [NC*HW];
__device__ float d_q  [NC*HW];
__device__ float d_p  [NC*HW];
__device__ __nv_bfloat16 d_qb[NC*HW];
__device__ __nv_bfloat16 d_kb[NC*HW];
__device__ __half d_vh[NC*HW];
__device__ float d_RW  [2*NH*HW];   // [Rh(80); Rw(80)]
__device__ float d_AB  [2*NH*HW];   // [ABh(80); ABw(80)]
__device__ float d_PAB [2*NH*HW];   // normalized [PA(80); PB(80)]
__device__ float d_W3  [ND*2*NH];   // [w3@efh | w3@efw]  m-major [256][160]
__device__ float d_o1  [NC*HW];
__device__ float d_op  [SPLIT*NC*HW];
__device__ float d_mp  [SPLIT*HW];
__device__ float d_lp  [SPLIT*HW];

// ---------------- tf32 GEMM (x1 conv) with register-prefetch pipeline --------
template<int EPI>
__global__ void __launch_bounds__(256) tgemm(
    const float* __restrict__ A, const float* __restrict__ B,
    float* __restrict__ C, int M, int K,
    const float* __restrict__ g, const float* __restrict__ bb,
    const float* __restrict__ mm, const float* __restrict__ vv)
{
    __shared__ float Wt[64 * 72];
    __shared__ float Bt[64 * 72];
    const int tid = threadIdx.x;
    const int wid = tid >> 5, lane = tid & 31;
    const int m0 = blockIdx.y * 64, n0 = blockIdx.x * 64;
    const int i0w = (wid & 3) * 16;
    const int jbase = (wid >> 2) * 32;
    const int lrow = lane >> 2, lk = lane & 3;
    const int mA = tid >> 2, kqA = (tid & 3) << 2;
    const int kkB = tid >> 4, n4B = (tid & 15) << 2;

    float sf[4][4];
    #pragma unroll
    for (int nt = 0; nt < 4; ++nt)
        #pragma unroll
        for (int e = 0; e < 4; ++e) sf[nt][e] = 0.f;

    float4 ar[4], br[4];
    #pragma unroll
    for (int i = 0; i < 4; ++i) {
        ar[i] = *(const float4*)&A[(size_t)(m0 + mA) * K + kqA + 16 * i];
        br[i] = *(const float4*)&B[(size_t)(kkB + 16 * i) * HW + n0 + n4B];
    }

    for (int kc = 0; kc < K; kc += 64) {
        #pragma unroll
        for (int i = 0; i < 4; ++i) {
            int k4 = kqA + 16 * i;
            Wt[(k4 + 0) * 72 + mA] = tf32r(ar[i].x);
            Wt[(k4 + 1) * 72 + mA] = tf32r(ar[i].y);
            Wt[(k4 + 2) * 72 + mA] = tf32r(ar[i].z);
            Wt[(k4 + 3) * 72 + mA] = tf32r(ar[i].w);
            int kk = kkB + 16 * i;
            float* bp = &Bt[kk * 72 + n4B];
            bp[0] = tf32r(br[i].x); bp[1] = tf32r(br[i].y);
            bp[2] = tf32r(br[i].z); bp[3] = tf32r(br[i].w);
        }
        __syncthreads();
        if (kc + 64 < K) {
            #pragma unroll
            for (int i = 0; i < 4; ++i) {
                ar[i] = *(const float4*)&A[(size_t)(m0 + mA) * K + kc + 64 + kqA + 16 * i];
                br[i] = *(const float4*)&B[(size_t)(kc + 64 + kkB + 16 * i) * HW + n0 + n4B];
            }
        }
        #pragma unroll
        for (int ks = 0; ks < 8; ++ks) {
            int k0 = ks * 8;
            uint32_t a0 = __float_as_uint(Wt[(k0 + lk) * 72 + i0w + lrow]);
            uint32_t a1 = __float_as_uint(Wt[(k0 + lk) * 72 + i0w + lrow + 8]);
            uint32_t a2 = __float_as_uint(Wt[(k0 + lk + 4) * 72 + i0w + lrow]);
            uint32_t a3 = __float_as_uint(Wt[(k0 + lk + 4) * 72 + i0w + lrow + 8]);
            #pragma unroll
            for (int np = 0; np < 4; ++np) {
                int ncol = jbase + np * 8 + lrow;
                uint32_t b0 = __float_as_uint(Bt[(k0 + lk) * 72 + ncol]);
                uint32_t b1 = __float_as_uint(Bt[(k0 + lk + 4) * 72 + ncol]);
                mma_tf32(sf[np], a0, a1, a2, a3, b0, b1);
            }
        }
        __syncthreads();
    }

    const int cc0 = 2 * lk;
    #pragma unroll
    for (int rr = 0; rr < 2; ++rr) {
        int gm = m0 + i0w + lrow + rr * 8;
        float sc = 0.f, sh = 0.f;
        if (EPI == 2) {
            sc = g[gm] * rsqrtf(vv[gm] + EPS);
            sh = bb[gm] - mm[gm] * sc;
        }
        #pragma unroll
        for (int nt = 0; nt < 4; ++nt) {
            float e0 = sf[nt][rr * 2 + 0];
            float e1 = sf[nt][rr * 2 + 1];
            if (EPI == 2) {
                e0 = e0 * sc + sh; e1 = e1 * sc + sh;
                e0 = e0 / (1.f + __expf(-e0));
                e1 = e1 / (1.f + __expf(-e1));
            }
            size_t idx = (size_t)gm * HW + n0 + jbase + nt * 8 + cc0;
            *(float2*)&C[idx] = make_float2(e0, e1);
        }
    }
}

// ---------------- fused 4-in-1 q/k/v/p projection (shared B tile) ------------
// Dynamic smem: Wt4[4][64*72] then Bt[64*72]  (92160 bytes)
#define P4_SM_BYTES ((4 * 64 * 72 + 64 * 72) * 4)
__global__ void __launch_bounds__(256) proj4(
    const float* __restrict__ x1,
    const float* __restrict__ wq, const float* __restrict__ bq,
    const float* __restrict__ wk, const float* __restrict__ bk,
    const float* __restrict__ wv, const float* __restrict__ bv,
    const float* __restrict__ wp, const float* __restrict__ bp,
    float* __restrict__ qf, __nv_bfloat16* __restrict__ qb,
    __nv_bfloat16* __restrict__ kb, __half* __restrict__ vh,
    float* __restrict__ pf)
{
    extern __shared__ float psm[];
    float* Bt = psm + 4 * 64 * 72;
    const int tid = threadIdx.x;
    const int wid = tid >> 5, lane = tid & 31;
    const int m0 = blockIdx.y * 64, n0 = blockIdx.x * 64;
    const int i0w = (wid & 3) * 16;
    const int jbase = (wid >> 2) * 32;
    const int lrow = lane >> 2, lk = lane & 3;
    const int mA = tid >> 2, kqA = (tid & 3) << 2;
    const int kkB = tid >> 4, n4B = (tid & 15) << 2;
    const float* Aw[4] = {wq, wk, wv, wp};

    float sf[4][4][4];
    #pragma unroll
    for (int w = 0; w < 4; ++w)
        #pragma unroll
        for (int nt = 0; nt < 4; ++nt)
            #pragma unroll
            for (int e = 0; e < 4; ++e) sf[w][nt][e] = 0.f;

    float4 br[4];
    #pragma unroll
    for (int i = 0; i < 4; ++i)
        br[i] = *(const float4*)&x1[(size_t)(kkB + 16 * i) * HW + n0 + n4B];

    for (int kc = 0; kc < NC; kc += 64) {
        // stage all 4 weight panels (direct loads; weights are L2-hot)
        #pragma unroll
        for (int w = 0; w < 4; ++w) {
            float* Wt = psm + w * 64 * 72;
            #pragma unroll
            for (int i = 0; i < 4; ++i) {
                int k4 = kqA + 16 * i;
                float4 a4 = *(const float4*)&Aw[w][(size_t)(m0 + mA) * NC + kc + k4];
                Wt[(k4 + 0) * 72 + mA] = tf32r(a4.x);
                Wt[(k4 + 1) * 72 + mA] = tf32r(a4.y);
                Wt[(k4 + 2) * 72 + mA] = tf32r(a4.z);
                Wt[(k4 + 3) * 72 + mA] = tf32r(a4.w);
            }
        }
        // stage shared B panel from prefetch
        #pragma unroll
        for (int i = 0; i < 4; ++i) {
            int kk = kkB + 16 * i;
            float* bp = &Bt[kk * 72 + n4B];
            bp[0] = tf32r(br[i].x); bp[1] = tf32r(br[i].y);
            bp[2] = tf32r(br[i].z); bp[3] = tf32r(br[i].w);
        }
        __syncthreads();
        if (kc + 64 < NC) {
            #pragma unroll
            for (int i = 0; i < 4; ++i)
                br[i] = *(const float4*)&x1[(size_t)(kc + 64 + kkB + 16 * i) * HW + n0 + n4B];
        }
        #pragma unroll
        for (int w = 0; w < 4; ++w) {
            const float* Wt = psm + w * 64 * 72;
            #pragma unroll
            for (int ks = 0; ks < 8; ++ks) {
                int k0 = ks * 8;
                uint32_t a0 = __float_as_uint(Wt[(k0 + lk) * 72 + i0w + lrow]);
                uint32_t a1 = __float_as_uint(Wt[(k0 + lk) * 72 + i0w + lrow + 8]);
                uint32_t a2 = __float_as_uint(Wt[(k0 + lk + 4) * 72 + i0w + lrow]);
                uint32_t a3 = __float_as_uint(Wt[(k0 + lk + 4) * 72 + i0w + lrow + 8]);
                #pragma unroll
                for (int np = 0; np < 4; ++np) {
                    int ncol = jbase + np * 8 + lrow;
                    uint32_t b0 = __float_as_uint(Bt[(k0 + lk) * 72 + ncol]);
                    uint32_t b1 = __float_as_uint(Bt[(k0 + lk + 4) * 72 + ncol]);
                    mma_tf32(sf[w][np], a0, a1, a2, a3, b0, b1);
                }
            }
        }
        __syncthreads();
    }

    const int cc0 = 2 * lk;
    const float* biasw[4] = {bq, bk, bv, bp};
    #pragma unroll
    for (int w = 0; w < 4; ++w) {
        #pragma unroll
        for (int rr = 0; rr < 2; ++rr) {
            int gm = m0 + i0w + lrow + rr * 8;
            float bsv = biasw[w][gm];
            #pragma unroll
            for (int nt = 0; nt < 4; ++nt) {
                float e0 = sf[w][nt][rr * 2 + 0] + bsv;
                float e1 = sf[w][nt][rr * 2 + 1] + bsv;
                size_t idx = (size_t)gm * HW + n0 + jbase + nt * 8 + cc0;
                if (w == 0) {
                    *(float2*)&qf[idx] = make_float2(e0, e1);
                    *(__nv_bfloat162*)&qb[idx] = __floats2bfloat162_rn(e0, e1);
                } else if (w == 1) {
                    *(__nv_bfloat162*)&kb[idx] = __floats2bfloat162_rn(e0, e1);
                } else if (w == 2) {
                    *(__half2*)&vh[idx] = __floats2half2_rn(e0, e1);
                } else {
                    *(float2*)&pf[idx] = make_float2(e0, e1);
                }
            }
        }
    }
}

// ---------------- stacked k-major GEMM (z=0: RW, z=1: AB; hoisted A ptr) -----
__global__ void __launch_bounds__(256) krgemm(
    const float* __restrict__ lo0, const float* __restrict__ hi0,
    const float* __restrict__ B0, float* __restrict__ C0,
    const float* __restrict__ lo1, const float* __restrict__ hi1,
    const float* __restrict__ B1, float* __restrict__ C1)
{
    __shared__ float Wt[64 * 72];
    __shared__ float Bt[64 * 72];
    const int z = blockIdx.z;
    const float* a_lo = z ? lo1 : lo0;
    const float* a_hi = z ? hi1 : hi0;
    const float* B    = z ? B1  : B0;
    float*       C    = z ? C1  : C0;
    const int tid = threadIdx.x;
    const int wid = tid >> 5, lane = tid & 31;
    const int m0 = blockIdx.y * 64, n0 = blockIdx.x * 64;
    const int i0w = (wid & 3) * 16;
    const int jbase = (wid >> 2) * 32;
    const int lrow = lane >> 2, lk = lane & 3;
    const int M = 2 * NH;
    const int kkB = tid >> 4, n4B = (tid & 15) << 2;
    const int m4A = (tid & 15) << 2;
    const int gmA = m0 + m4A;
    // hoist the lo/hi row selection (loop-invariant)
    const bool aok = (gmA < 2 * NH);
    const float* aptr = (gmA < NH) ? (a_lo + gmA)
                                   : (aok ? (a_hi + gmA - NH) : a_lo);

    float sf[4][4];
    #pragma unroll
    for (int nt = 0; nt < 4; ++nt)
        #pragma unroll
        for (int e = 0; e < 4; ++e) sf[nt][e] = 0.f;

    float4 ar[4], br[4];
    #pragma unroll
    for (int i = 0; i < 4; ++i) {
        int kk = kkB + 16 * i;
        ar[i] = aok ? *(const float4*)&aptr[(size_t)kk * NH]
                    : make_float4(0.f, 0.f, 0.f, 0.f);
        br[i] = *(const float4*)&B[(size_t)kk * HW + n0 + n4B];
    }

    for (int kc = 0; kc < NC; kc += 64) {
        #pragma unroll
        for (int i = 0; i < 4; ++i) {
            int kk = kkB + 16 * i;
            float* wp = &Wt[kk * 72 + m4A];
            wp[0] = tf32r(ar[i].x); wp[1] = tf32r(ar[i].y);
            wp[2] = tf32r(ar[i].z); wp[3] = tf32r(ar[i].w);
            float* bp = &Bt[kk * 72 + n4B];
            bp[0] = tf32r(br[i].x); bp[1] = tf32r(br[i].y);
            bp[2] = tf32r(br[i].z); bp[3] = tf32r(br[i].w);
        }
        __syncthreads();
        if (kc + 64 < NC) {
            #pragma unroll
            for (int i = 0; i < 4; ++i) {
                int kk = kc + 64 + kkB + 16 * i;
                ar[i] = aok ? *(const float4*)&aptr[(size_t)kk * NH]
                            : make_float4(0.f, 0.f, 0.f, 0.f);
                br[i] = *(const float4*)&B[(size_t)kk * HW + n0 + n4B];
            }
        }
        #pragma unroll
        for (int ks = 0; ks < 8; ++ks) {
            int k0 = ks * 8;
            uint32_t a0 = __float_as_uint(Wt[(k0 + lk) * 72 + i0w + lrow]);
            uint32_t a1 = __float_as_uint(Wt[(k0 + lk) * 72 + i0w + lrow + 8]);
            uint32_t a2 = __float_as_uint(Wt[(k0 + lk + 4) * 72 + i0w + lrow]);
            uint32_t a3 = __float_as_uint(Wt[(k0 + lk + 4) * 72 + i0w + lrow + 8]);
            #pragma unroll
            for (int np = 0; np < 4; ++np) {
                int ncol = jbase + np * 8 + lrow;
                uint32_t b0 = __float_as_uint(Bt[(k0 + lk) * 72 + ncol]);
                uint32_t b1 = __float_as_uint(Bt[(k0 + lk + 4) * 72 + ncol]);
                mma_tf32(sf[np], a0, a1, a2, a3, b0, b1);
            }
        }
        __syncthreads();
    }

    const int cc0 = 2 * lk;
    #pragma unroll
    for (int rr = 0; rr < 2; ++rr) {
        int gm = m0 + i0w + lrow + rr * 8;
        if (gm >= M) continue;
        #pragma unroll
        for (int nt = 0; nt < 4; ++nt) {
            size_t idx = (size_t)gm * HW + n0 + jbase + nt * 8 + cc0;
            *(float2*)&C[idx] = make_float2(sf[nt][rr * 2 + 0], sf[nt][rr * 2 + 1]);
        }
    }
}

// ---------------- expnorm: single-store softmax over 80 rows ------------------
__global__ void expnorm(const float* __restrict__ AB, float* __restrict__ PAB)
{
    int gid = blockIdx.x * blockDim.x + threadIdx.x;
    if (gid >= 2 * HW) return;
    int h = (gid >= HW) ? 1 : 0;
    int i = gid - h * HW;
    const float* src = AB  + (size_t)h * NH * HW;
    float*       dst = PAB + (size_t)h * NH * HW;
    float s = 0.f;
    #pragma unroll 8
    for (int t = 0; t < NH; ++t) s += __expf(src[t * HW + i]);
    float inv = 1.f / s;
    #pragma unroll 8
    for (int t = 0; t < NH; ++t)
        dst[t * HW + i] = __expf(src[t * HW + i]) * inv;
}

// ---------------- W3 = [w3@efh | w3@efw]  ([256][160], m-major) --------------
__global__ void __launch_bounds__(192) w3eff_kernel(
    const float* __restrict__ w3, const float* __restrict__ efh,
    const float* __restrict__ efw, float* __restrict__ W)
{
    __shared__ float sw3[NC];
    const int m = blockIdx.x;
    const int t = threadIdx.x;
    if (t < NC) sw3[t] = w3[(size_t)m * NC + t];
    __syncthreads();
    if (t >= 2 * NH) return;
    const float* ef = (t < NH) ? (efh + t) : (efw + t - NH);
    float sum = 0.f;
    #pragma unroll 16
    for (int c = 0; c < NC; ++c)
        sum += sw3[c] * ef[(size_t)c * NH];
    W[(size_t)m * 160 + t] = sum;
}

// ---------------- fused final (prefetched, dual source) ----------------------
__global__ void __launch_bounds__(256) final_gemm(
    const float* __restrict__ w2, const float* __restrict__ o1,
    const float* __restrict__ g2, const float* __restrict__ b2,
    const float* __restrict__ m2, const float* __restrict__ v2,
    const float* __restrict__ W3, const float* __restrict__ PAB,
    const float* __restrict__ g3, const float* __restrict__ b3,
    const float* __restrict__ m3, const float* __restrict__ v3,
    const float* __restrict__ x, float* __restrict__ out)
{
    __shared__ float Wt[64 * 72];
    __shared__ float Bt[64 * 72];
    const int tid = threadIdx.x;
    const int wid = tid >> 5, lane = tid & 31;
    const int m0 = blockIdx.y * 64, n0 = blockIdx.x * 64;
    const int i0w = (wid & 3) * 16;
    const int jbase = (wid >> 2) * 32;
    const int lrow = lane >> 2, lk = lane & 3;
    const int mA = tid >> 2, kqA = (tid & 3) << 2;
    const int kkB = tid >> 4, n4B = (tid & 15) << 2;

    float keep[4][4];
    float sf[4][4];
    #pragma unroll
    for (int nt = 0; nt < 4; ++nt)
        #pragma unroll
        for (int e = 0; e < 4; ++e) sf[nt][e] = 0.f;

    float4 ar[4], br[4];
    #pragma unroll
    for (int i = 0; i < 4; ++i) {
        ar[i] = *(const float4*)&w2[(size_t)(m0 + mA) * NC + kqA + 16 * i];
        br[i] = *(const float4*)&o1[(size_t)(kkB + 16 * i) * HW + n0 + n4B];
    }

    #pragma unroll
    for (int src = 0; src < 2; ++src) {
        const int Kp = src ? 160 : NC;
        for (int kc = 0; kc < Kp; kc += 64) {
            const int ck = (Kp - kc < 64) ? (Kp - kc) : 64;
            #pragma unroll
            for (int i = 0; i < 4; ++i) {
                int k4 = kqA + 16 * i;
                if (k4 < ck) {
                    Wt[(k4 + 0) * 72 + mA] = tf32r(ar[i].x);
                    Wt[(k4 + 1) * 72 + mA] = tf32r(ar[i].y);
                    Wt[(k4 + 2) * 72 + mA] = tf32r(ar[i].z);
                    Wt[(k4 + 3) * 72 + mA] = tf32r(ar[i].w);
                }
                int kk = kkB + 16 * i;
                if (kk < ck) {
                    float* bp = &Bt[kk * 72 + n4B];
                    bp[0] = tf32r(br[i].x); bp[1] = tf32r(br[i].y);
                    bp[2] = tf32r(br[i].z); bp[3] = tf32r(br[i].w);
                }
            }
            __syncthreads();
            {
                int srcN = src, kcN = kc + 64;
                if (kcN >= Kp) { srcN = src + 1; kcN = 0; }
                if (srcN < 2) {
                    const float* ApN = srcN ? W3 : w2;
                    const float* BpN = srcN ? PAB : o1;
                    int KpN = srcN ? 160 : NC;
                    int ckN = (KpN - kcN < 64) ? (KpN - kcN) : 64;
                    #pragma unroll
                    for (int i = 0; i < 4; ++i) {
                        int k4 = kqA + 16 * i;
                        if (k4 < ckN)
                            ar[i] = *(const float4*)&ApN[(size_t)(m0 + mA) * KpN + kcN + k4];
                        int kk = kkB + 16 * i;
                        if (kk < ckN)
                            br[i] = *(const float4*)&BpN[(size_t)(kcN + kk) * HW + n0 + n4B];
                    }
                }
            }
            const int nks = ck >> 3;
            for (int ks = 0; ks < nks; ++ks) {
                int k0 = ks * 8;
                uint32_t a0 = __float_as_uint(Wt[(k0 + lk) * 72 + i0w + lrow]);
                uint32_t a1 = __float_as_uint(Wt[(k0 + lk) * 72 + i0w + lrow + 8]);
                uint32_t a2 = __float_as_uint(Wt[(k0 + lk + 4) * 72 + i0w + lrow]);
                uint32_t a3 = __float_as_uint(Wt[(k0 + lk + 4) * 72 + i0w + lrow + 8]);
                #pragma unroll
                for (int np = 0; np < 4; ++np) {
                    int ncol = jbase + np * 8 + lrow;
                    uint32_t b0 = __float_as_uint(Bt[(k0 + lk) * 72 + ncol]);
                    uint32_t b1 = __float_as_uint(Bt[(k0 + lk + 4) * 72 + ncol]);
                    mma_tf32(sf[np], a0, a1, a2, a3, b0, b1);
                }
            }
            __syncthreads();
        }
        const float* gg  = src ? g3 : g2;
        const float* bbp = src ? b3 : b2;
        const float* mmp = src ? m3 : m2;
        const float* vvp = src ? v3 : v2;
        #pragma unroll
        for (int rr = 0; rr < 2; ++rr) {
            int gm = m0 + i0w + lrow + rr * 8;
            float sc = gg[gm] * rsqrtf(vvp[gm] + EPS);
            float sh = bbp[gm] - mmp[gm] * sc;
            #pragma unroll
            for (int nt = 0; nt < 4; ++nt) {
                #pragma unroll
                for (int e2 = 0; e2 < 2; ++e2) {
                    float val = sf[nt][rr * 2 + e2] * sc + sh;
                    val = val / (1.f + __expf(-val));
                    if (src == 0) { keep[nt][rr * 2 + e2] = val; sf[nt][rr * 2 + e2] = 0.f; }
                    else          { keep[nt][rr * 2 + e2] += val; }
                }
            }
        }
    }

    const int cc0 = 2 * lk;
    #pragma unroll
    for (int rr = 0; rr < 2; ++rr) {
        int gm = m0 + i0w + lrow + rr * 8;
        #pragma unroll
        for (int nt = 0; nt < 4; ++nt) {
            size_t idx = (size_t)gm * HW + n0 + jbase + nt * 8 + cc0;
            float2 x2 = *(const float2*)&x[idx];
            *(float2*)&out[idx] = make_float2(keep[nt][rr * 2 + 0] + x2.x,
                                              keep[nt][rr * 2 + 1] + x2.y);
        }
    }
}

// ---------------- branch-1 flash attention: 4 fat warps, occ 2 (R11) ---------
#define QS_OFF   0               // bf16 [128][72]
#define KS_OFF   18432           // bf16 [128][72]
#define VS_OFF   36864           // f16  [128][72]
#define RB_OFF   55296           // f16  [64][72] fused Rw+Rh bias
#define FL_SM_BYTES 64512

__global__ void __launch_bounds__(128, 2) flash_kernel(
    const __nv_bfloat16* __restrict__ q, const __nv_bfloat16* __restrict__ k,
    const __half* __restrict__ v, const float* __restrict__ Rh,
    const float* __restrict__ Rw, float* __restrict__ op,
    float* __restrict__ mp, float* __restrict__ lp)
{
    extern __shared__ char smc[];
    __half* RbH = (__half*)(smc + RB_OFF);

    const int tid  = threadIdx.x;
    const int wid  = tid >> 5, lane = tid & 31;
    const int lr   = lane & 7, gq = lane >> 3;
    const int lrowq = lane >> 2, lk = lane & 3;
    const int i0   = blockIdx.x * 64;
    const int spl  = blockIdx.y;
    const int t0   = (spl * 100) / SPLIT;
    const int t1   = ((spl + 1) * 100) / SPLIT;
    const int i0w  = wid * 16;
    const float L2E = 1.4426950408889634f;

    const uint32_t qsb = (uint32_t)__cvta_generic_to_shared(smc + QS_OFF);
    const uint32_t ksb = (uint32_t)__cvta_generic_to_shared(smc + KS_OFF);
    const uint32_t vsb = (uint32_t)__cvta_generic_to_shared(smc + VS_OFF);

    // prologue: Q, K(t0), V(t0) via cp.async (3 groups)
    {
        #pragma unroll
        for (int it = 0; it < 8; ++it) {
            int ch = tid + it * 128;
            int c = ch >> 3, j8 = (ch & 7) * 8;
            cpa16(qsb + (uint32_t)((c * 72 + j8) * 2), &q[(size_t)c * HW + i0 + j8]);
        }
        CPA_COMMIT();
        int j0n = t0 * 64;
        #pragma unroll
        for (int it = 0; it < 8; ++it) {
            int ch = tid + it * 128;
            int c = ch >> 3, j8 = (ch & 7) * 8;
            cpa16(ksb + (uint32_t)((c * 72 + j8) * 2), &k[(size_t)c * HW + j0n + j8]);
        }
        CPA_COMMIT();
        #pragma unroll
        for (int it = 0; it < 8; ++it) {
            int ch = tid + it * 128;
            int c = ch >> 3, j8 = (ch & 7) * 8;
            cpa16(vsb + (uint32_t)((c * 72 + j8) * 2), &v[(size_t)c * HW + j0n + j8]);
        }
        CPA_COMMIT();
    }
    asm volatile("cp.async.wait_group 2;");   // Q landed
    __syncthreads();

    // hoist Q fragments (loop-invariant): 8 k-steps x 4 regs
    uint32_t qf[8][4];
    #pragma unroll
    for (int ks = 0; ks < 8; ++ks)
        ldsm4t(qf[ks][0], qf[ks][1], qf[ks][2], qf[ks][3],
               qsb + (uint32_t)(((ks * 16 + lr + (gq >> 1) * 8) * 72
                                + i0w + (gq & 1) * 8) * 2));

    float d[16][4];
    #pragma unroll
    for (int nt = 0; nt < 16; ++nt)
        #pragma unroll
        for (int e = 0; e < 4; ++e) d[nt][e] = 0.f;
    float m0v = -1e30f, m1v = -1e30f, l0v = 0.f, l1v = 0.f;
    const int r0 = i0w + lrowq, r1 = r0 + 8;

    for (int t = t0; t < t1; ++t) {
        const int j0 = t * 64;
        const bool more = (t + 1 < t1);

        // stage fused bias tile fp16 (safe: previous softmax done at sync C)
        #pragma unroll
        for (int e = 0; e < 8; ++e) {
            int ee = tid + e * 128;
            int row = ee >> 4, c4 = (ee & 15) << 2;
            int gi = i0 + row;
            float4 a = *(const float4*)&Rw[(gi % 80) * HW + j0 + c4];
            float4 b = *(const float4*)&Rh[(gi / 80) * HW + j0 + c4];
            __half2* dst = (__half2*)&RbH[row * 72 + c4];
            dst[0] = __floats2half2_rn(a.x + b.x, a.y + b.y);
            dst[1] = __floats2half2_rn(a.z + b.z, a.w + b.w);
        }
        asm volatile("cp.async.wait_group 1;");   // K(t) landed
        __syncthreads();                          // A: K + bias visible

        // ---- QK^T (bf16), full 64 j per warp ----
        float sf[8][4];
        #pragma unroll
        for (int nb = 0; nb < 8; ++nb)
            #pragma unroll
            for (int e = 0; e < 4; ++e) sf[nb][e] = 0.f;

        #pragma unroll
        for (int ks = 0; ks < 8; ++ks) {
            #pragma unroll
            for (int jn = 0; jn < 4; ++jn) {
                uint32_t b0, b1, b2, b3;
                ldsm4t(b0, b1, b2, b3,
                       ksb + (uint32_t)(((ks * 16 + lr + (gq & 1) * 8) * 72
                                        + jn * 16 + (gq >> 1) * 8) * 2));
                mma_bf16(sf[jn * 2],     qf[ks][0], qf[ks][1], qf[ks][2], qf[ks][3], b0, b1);
                mma_bf16(sf[jn * 2 + 1], qf[ks][0], qf[ks][1], qf[ks][2], qf[ks][3], b2, b3);
            }
        }
        asm volatile("cp.async.wait_group 0;");   // V(t) landed
        __syncthreads();                          // B: Ks free, Vs visible

        if (more) {                               // K(t+1) in place
            int j0n = (t + 1) * 64;
            #pragma unroll
            for (int it = 0; it < 8; ++it) {
                int ch = tid + it * 128;
                int c = ch >> 3, j8 = (ch & 7) * 8;
                cpa16(ksb + (uint32_t)((c * 72 + j8) * 2), &k[(size_t)c * HW + j0n + j8]);
            }
            CPA_COMMIT();
        }

        // ---- softmax entirely warp-local (regs + quad shfl) ----
        #pragma unroll
        for (int nb = 0; nb < 8; ++nb) {
            int col = nb * 8 + 2 * lk;
            float2 b0 = __half22float2(*(__half2*)&RbH[r0 * 72 + col]);
            float2 b1 = __half22float2(*(__half2*)&RbH[r1 * 72 + col]);
            sf[nb][0] += b0.x; sf[nb][1] += b0.y;
            sf[nb][2] += b1.x; sf[nb][3] += b1.y;
        }
        float mx0 = -1e30f, mx1 = -1e30f;
        #pragma unroll
        for (int nb = 0; nb < 8; ++nb) {
            mx0 = fmaxf(mx0, fmaxf(sf[nb][0], sf[nb][1]));
            mx1 = fmaxf(mx1, fmaxf(sf[nb][2], sf[nb][3]));
        }
        mx0 = fmaxf(mx0, __shfl_xor_sync(0xffffffffu, mx0, 1));
        mx0 = fmaxf(mx0, __shfl_xor_sync(0xffffffffu, mx0, 2));
        mx1 = fmaxf(mx1, __shfl_xor_sync(0xffffffffu, mx1, 1));
        mx1 = fmaxf(mx1, __shfl_xor_sync(0xffffffffu, mx1, 2));
        float nm0 = fmaxf(m0v, mx0), nm1 = fmaxf(m1v, mx1);
        float f0 = exp2f((m0v - nm0) * L2E);
        float f1 = exp2f((m1v - nm1) * L2E);
        uint32_t ph[8][2];
        float s0 = 0.f, s1 = 0.f;
        #pragma unroll
        for (int nb = 0; nb < 8; ++nb) {
            float u0 = (sf[nb][0] - nm0) * L2E, u1 = (sf[nb][1] - nm0) * L2E;
            float u2 = (sf[nb][2] - nm1) * L2E, u3 = (sf[nb][3] - nm1) * L2E;
            uint32_t p0, p1;
            asm("cvt.rn.f16x2.f32 %0, %1, %2;" : "=r"(p0) : "f"(u1), "f"(u0));
            asm("ex2.approx.f16x2 %0, %0;" : "+r"(p0));
            asm("cvt.rn.f16x2.f32 %0, %1, %2;" : "=r"(p1) : "f"(u3), "f"(u2));
            asm("ex2.approx.f16x2 %0, %0;" : "+r"(p1));
            ph[nb][0] = p0; ph[nb][1] = p1;
            float2 e0 = __half22float2(*reinterpret_cast<__half2*>(&p0));
            float2 e1 = __half22float2(*reinterpret_cast<__half2*>(&p1));
            s0 += e0.x + e0.y;
            s1 += e1.x + e1.y;
        }
        s0 += __shfl_xor_sync(0xffffffffu, s0, 1);
        s0 += __shfl_xor_sync(0xffffffffu, s0, 2);
        s1 += __shfl_xor_sync(0xffffffffu, s1, 1);
        s1 += __shfl_xor_sync(0xffffffffu, s1, 2);
        l0v = l0v * f0 + s0;  m0v = nm0;
        l1v = l1v * f1 + s1;  m1v = nm1;
        #pragma unroll
        for (int nt = 0; nt < 16; ++nt) {
            d[nt][0] *= f0; d[nt][1] *= f0;
            d[nt][2] *= f1; d[nt][3] *= f1;
        }

        // ---- P @ V^T (fp16): A = register P frags, k = 64 j, n = 128 c ----
        #pragma unroll
        for (int ks = 0; ks < 4; ++ks) {
            uint32_t a0 = ph[2 * ks][0], a1 = ph[2 * ks][1];
            uint32_t a2 = ph[2 * ks + 1][0], a3 = ph[2 * ks + 1][1];
            #pragma unroll
            for (int np = 0; np < 8; ++np) {
                uint32_t b0, b1, b2, b3;
                ldsm4(b0, b1, b2, b3,
                      vsb + (uint32_t)(((np * 16 + lr + (gq >> 1) * 8) * 72
                                       + ks * 16 + (gq & 1) * 8) * 2));
                mma_f16(d[np * 2],     a0, a1, a2, a3, b0, b1);
                mma_f16(d[np * 2 + 1], a0, a1, a2, a3, b2, b3);
            }
        }
        __syncthreads();                          // C: Vs free, bias free

        if (more) {                               // V(t+1)
            int j0n = (t + 1) * 64;
            #pragma unroll
            for (int it = 0; it < 8; ++it) {
                int ch = tid + it * 128;
                int c = ch >> 3, j8 = (ch & 7) * 8;
                cpa16(vsb + (uint32_t)((c * 72 + j8) * 2), &v[(size_t)c * HW + j0n + j8]);
            }
            CPA_COMMIT();
        }
    }

    // ---- epilogue: warp owns 16 rows x all 128 channels; direct writes ----
    #pragma unroll
    for (int nt = 0; nt < 16; ++nt) {
        int c = nt * 8 + 2 * lk;
        op[(size_t)(spl * NC + c)     * HW + i0 + r0] = d[nt][0];
        op[(size_t)(spl * NC + c + 1) * HW + i0 + r0] = d[nt][1];
        op[(size_t)(spl * NC + c)     * HW + i0 + r1] = d[nt][2];
        op[(size_t)(spl * NC + c + 1) * HW + i0 + r1] = d[nt][3];
    }
    if (lk == 0) {
        mp[spl * HW + i0 + r0] = m0v;
        mp[spl * HW + i0 + r1] = m1v;
        lp[spl * HW + i0 + r0] = l0v;
        lp[spl * HW + i0 + r1] = l1v;
    }
}

// ---------------- split-j combine (channel-parallel, scalar — R11 config) ----
__global__ void combine_kernel(const float* __restrict__ op,
                               const float* __restrict__ mp,
                               const float* __restrict__ lp,
                               float* __restrict__ out1)
{
    int i = blockIdx.x * blockDim.x + threadIdx.x;
    if (i >= HW) return;
    int c0 = blockIdx.y * 8;
    float m[SPLIT], w[SPLIT];
    float M = -1e30f;
    #pragma unroll
    for (int s = 0; s < SPLIT; ++s) { m[s] = mp[s * HW + i]; M = fmaxf(M, m[s]); }
    float L = 0.f;
    #pragma unroll
    for (int s = 0; s < SPLIT; ++s) { w[s] = __expf(m[s] - M); L += lp[s * HW + i] * w[s]; }
    float inv = 1.f / L;
    for (int c = c0; c < c0 + 8; ++c) {
        float acc = 0.f;
        #pragma unroll
        for (int s = 0; s < SPLIT; ++s)
            acc += op[((size_t)(s * NC + c)) * HW + i] * w[s];
        out1[(size_t)c * HW + i] = acc * inv;
    }
}

// -------------------------------- launch -------------------------------------
extern "C" void kernel_launch(void* const* d_in, const int* in_sizes, int n_in,
                              void* d_out, int out_size)
{
    (void)in_sizes; (void)n_in; (void)out_size;
    const float* x    = (const float*)d_in[0];
    const float* w1   = (const float*)d_in[1];
    const float* g1   = (const float*)d_in[2];
    const float* b1   = (const float*)d_in[3];
    const float* m1   = (const float*)d_in[4];
    const float* v1   = (const float*)d_in[5];
    const float* w2   = (const float*)d_in[6];
    const float* g2   = (const float*)d_in[7];
    const float* b2   = (const float*)d_in[8];
    const float* m2   = (const float*)d_in[9];
    const float* v2   = (const float*)d_in[10];
    const float* w3   = (const float*)d_in[11];
    const float* g3   = (const float*)d_in[12];
    const float* b3   = (const float*)d_in[13];
    const float* m3   = (const float*)d_in[14];
    const float* v3   = (const float*)d_in[15];
    const float* wq   = (const float*)d_in[16];
    const float* bq   = (const float*)d_in[17];
    const float* wk   = (const float*)d_in[18];
    const float* bk   = (const float*)d_in[19];
    const float* wv   = (const float*)d_in[20];
    const float* bv   = (const float*)d_in[21];
    const float* wp   = (const float*)d_in[22];
    const float* bp   = (const float*)d_in[23];
    const float* relh = (const float*)d_in[24];
    const float* relw = (const float*)d_in[25];
    const float* efh  = (const float*)d_in[26];
    const float* efw  = (const float*)d_in[27];
    float* out = (float*)d_out;

    float *px1, *pq, *pp, *pRW, *pAB, *pPAB, *pW3, *po1, *pop, *pmp, *plp;
    __nv_bfloat16 *pqb, *pkb;
    __half *pvh;
    cudaGetSymbolAddress((void**)&px1, d_x1);
    cudaGetSymbolAddress((void**)&pq,  d_q);
    cudaGetSymbolAddress((void**)&pp,  d_p);
    cudaGetSymbolAddress((void**)&pqb, d_qb);
    cudaGetSymbolAddress((void**)&pkb, d_kb);
    cudaGetSymbolAddress((void**)&pvh, d_vh);
    cudaGetSymbolAddress((void**)&pRW, d_RW);
    cudaGetSymbolAddress((void**)&pAB, d_AB);
    cudaGetSymbolAddress((void**)&pPAB, d_PAB);
    cudaGetSymbolAddress((void**)&pW3, d_W3);
    cudaGetSymbolAddress((void**)&po1, d_o1);
    cudaGetSymbolAddress((void**)&pop, d_op);
    cudaGetSymbolAddress((void**)&pmp, d_mp);
    cudaGetSymbolAddress((void**)&plp, d_lp);

    cudaFuncSetAttribute(flash_kernel,
        cudaFuncAttributeMaxDynamicSharedMemorySize, FL_SM_BYTES);
    cudaFuncSetAttribute(proj4,
        cudaFuncAttributeMaxDynamicSharedMemorySize, P4_SM_BYTES);

    dim3 g100_2(100, 2), g100_4(100, 4);
    dim3 gkr(100, 3, 2), gfl(100, SPLIT), gcmb(25, 16);

    // [0] W3 = [w3@efh | w3@efw]
    w3eff_kernel<<<ND, 192>>>(w3, efh, efw, pW3);
    // [1] x1 = SiLU(BN(w1 @ x))
    tgemm<2><<<g100_2, 256>>>(w1, x, px1, NC, ND, g1, b1, m1, v1);
    // [2] fused 4-in-1 q/k/v/p projections (shared B tile; fp32 q,p; bf16 q,k; fp16 v)
    proj4<<<g100_2, 256, P4_SM_BYTES>>>(px1, wq, bq, wk, bk, wv, bv, wp, bp,
        pq, pqb, pkb, pvh, pp);
    // [3] z=0: [Rh;Rw] = [rel_h;rel_w]^T q;  z=1: [ABh;ABw] = [ef_h;ef_w]^T p
    krgemm<<<gkr, 256>>>(relh, relw, pq, pRW, efh, efw, pp, pAB);
    // [4] PAB = per-column softmax of both halves (single-store)
    expnorm<<<50, 256>>>(pAB, pPAB);
    // [5] flash attention (4 fat warps, occ 2 — known-good R11 config)
    flash_kernel<<<gfl, 128, FL_SM_BYTES>>>(pqb, pkb, pvh,
        pRW, pRW + NH * HW, pop, pmp, plp);
    // [6] combine split partials -> out1 (scalar, 400 CTAs — R11 config)
    combine_kernel<<<gcmb, 256>>>(pop, pmp, plp, po1);
    // [7] out = x + SiLU(BN2(w2@o1)) + SiLU(BN3(W3@PAB))
    final_gemm<<<g100_4, 256>>>(w2, po1, g2, b2, m2, v2,
        pW3, pPAB, g3, b3, m3, v3, x, out);
}

// round 16
// speedup vs baseline: 1.5004x; 1.5004x over previous
#include <cuda_runtime.h>
#include <cuda_bf16.h>
#include <cuda_fp16.h>
#include <cstdint>

#define EPS 1e-5f
#define HW 6400
#define NC 128
#define ND 256
#define NH 80
#define SPLIT 8

// ---------------- tensor-core helpers ----------------------------------------
__device__ __forceinline__ void ldsm4(uint32_t& r0, uint32_t& r1,
                                      uint32_t& r2, uint32_t& r3, uint32_t a) {
    asm volatile("ldmatrix.sync.aligned.m8n8.x4.shared.b16 {%0,%1,%2,%3},[%4];"
        : "=r"(r0), "=r"(r1), "=r"(r2), "=r"(r3) : "r"(a));
}
__device__ __forceinline__ void ldsm4t(uint32_t& r0, uint32_t& r1,
                                       uint32_t& r2, uint32_t& r3, uint32_t a) {
    asm volatile("ldmatrix.sync.aligned.m8n8.x4.trans.shared.b16 {%0,%1,%2,%3},[%4];"
        : "=r"(r0), "=r"(r1), "=r"(r2), "=r"(r3) : "r"(a));
}
__device__ __forceinline__ void mma_bf16(float* d, uint32_t a0, uint32_t a1,
                                         uint32_t a2, uint32_t a3,
                                         uint32_t b0, uint32_t b1) {
    asm volatile("mma.sync.aligned.m16n8k16.row.col.f32.bf16.bf16.f32 "
        "{%0,%1,%2,%3},{%4,%5,%6,%7},{%8,%9},{%0,%1,%2,%3};"
        : "+f"(d[0]), "+f"(d[1]), "+f"(d[2]), "+f"(d[3])
        : "r"(a0), "r"(a1), "r"(a2), "r"(a3), "r"(b0), "r"(b1));
}
__device__ __forceinline__ void mma_f16(float* d, uint32_t a0, uint32_t a1,
                                        uint32_t a2, uint32_t a3,
                                        uint32_t b0, uint32_t b1) {
    asm volatile("mma.sync.aligned.m16n8k16.row.col.f32.f16.f16.f32 "
        "{%0,%1,%2,%3},{%4,%5,%6,%7},{%8,%9},{%0,%1,%2,%3};"
        : "+f"(d[0]), "+f"(d[1]), "+f"(d[2]), "+f"(d[3])
        : "r"(a0), "r"(a1), "r"(a2), "r"(a3), "r"(b0), "r"(b1));
}
__device__ __forceinline__ void mma_tf32(float* d, uint32_t a0, uint32_t a1,
                                         uint32_t a2, uint32_t a3,
                                         uint32_t b0, uint32_t b1) {
    asm volatile("mma.sync.aligned.m16n8k8.row.col.f32.tf32.tf32.f32 "
        "{%0,%1,%2,%3},{%4,%5,%6,%7},{%8,%9},{%0,%1,%2,%3};"
        : "+f"(d[0]), "+f"(d[1]), "+f"(d[2]), "+f"(d[3])
        : "r"(a0), "r"(a1), "r"(a2), "r"(a3), "r"(b0), "r"(b1));
}
__device__ __forceinline__ float tf32r(float x) {
    uint32_t r;
    asm("cvt.rna.tf32.f32 %0, %1;" : "=r"(r) : "f"(x));
    return __uint_as_float(r);
}
__device__ __forceinline__ void cpa16(uint32_t s, const void* g) {
    asm volatile("cp.async.cg.shared.global [%0], [%1], 16;" :: "r"(s), "l"(g));
}
#define CPA_COMMIT() asm volatile("cp.async.commit_group;")

// ---------------- scratch (static device globals; no allocation) -------------
__device__ float d_x1 [NC*HW];
__device__ float d_q  [NC*HW];
__device__ float d_p  [NC*HW];
__device__ __nv_bfloat16 d_qb[NC*HW];
__device__ __nv_bfloat16 d_kb[NC*HW];
__device__ __half d_vh[NC*HW];
__device__ float d_RW  [2*NH*HW];   // [Rh(80); Rw(80)]
__device__ float d_AB  [2*NH*HW];   // [ABh(80); ABw(80)]
__device__ float d_PAB [2*NH*HW];   // normalized [PA(80); PB(80)]
__device__ float d_W3  [ND*2*NH];   // [w3@efh | w3@efw]  m-major [256][160]
__device__ float d_o1  [NC*HW];
__device__ float d_op  [SPLIT*NC*HW];
__device__ float d_mp  [SPLIT*HW];
__device__ float d_lp  [SPLIT*HW];

// ---------------- tf32 GEMM (x1 conv) with register-prefetch pipeline --------
template<int EPI>
__global__ void __launch_bounds__(256) tgemm(
    const float* __restrict__ A, const float* __restrict__ B,
    float* __restrict__ C, int M, int K,
    const float* __restrict__ g, const float* __restrict__ bb,
    const float* __restrict__ mm, const float* __restrict__ vv)
{
    __shared__ float Wt[64 * 72];
    __shared__ float Bt[64 * 72];
    const int tid = threadIdx.x;
    const int wid = tid >> 5, lane = tid & 31;
    const int m0 = blockIdx.y * 64, n0 = blockIdx.x * 64;
    const int i0w = (wid & 3) * 16;
    const int jbase = (wid >> 2) * 32;
    const int lrow = lane >> 2, lk = lane & 3;
    const int mA = tid >> 2, kqA = (tid & 3) << 2;
    const int kkB = tid >> 4, n4B = (tid & 15) << 2;

    float sf[4][4];
    #pragma unroll
    for (int nt = 0; nt < 4; ++nt)
        #pragma unroll
        for (int e = 0; e < 4; ++e) sf[nt][e] = 0.f;

    float4 ar[4], br[4];
    #pragma unroll
    for (int i = 0; i < 4; ++i) {
        ar[i] = *(const float4*)&A[(size_t)(m0 + mA) * K + kqA + 16 * i];
        br[i] = *(const float4*)&B[(size_t)(kkB + 16 * i) * HW + n0 + n4B];
    }

    for (int kc = 0; kc < K; kc += 64) {
        #pragma unroll
        for (int i = 0; i < 4; ++i) {
            int k4 = kqA + 16 * i;
            Wt[(k4 + 0) * 72 + mA] = tf32r(ar[i].x);
            Wt[(k4 + 1) * 72 + mA] = tf32r(ar[i].y);
            Wt[(k4 + 2) * 72 + mA] = tf32r(ar[i].z);
            Wt[(k4 + 3) * 72 + mA] = tf32r(ar[i].w);
            int kk = kkB + 16 * i;
            float* bp = &Bt[kk * 72 + n4B];
            bp[0] = tf32r(br[i].x); bp[1] = tf32r(br[i].y);
            bp[2] = tf32r(br[i].z); bp[3] = tf32r(br[i].w);
        }
        __syncthreads();
        if (kc + 64 < K) {
            #pragma unroll
            for (int i = 0; i < 4; ++i) {
                ar[i] = *(const float4*)&A[(size_t)(m0 + mA) * K + kc + 64 + kqA + 16 * i];
                br[i] = *(const float4*)&B[(size_t)(kc + 64 + kkB + 16 * i) * HW + n0 + n4B];
            }
        }
        #pragma unroll
        for (int ks = 0; ks < 8; ++ks) {
            int k0 = ks * 8;
            uint32_t a0 = __float_as_uint(Wt[(k0 + lk) * 72 + i0w + lrow]);
            uint32_t a1 = __float_as_uint(Wt[(k0 + lk) * 72 + i0w + lrow + 8]);
            uint32_t a2 = __float_as_uint(Wt[(k0 + lk + 4) * 72 + i0w + lrow]);
            uint32_t a3 = __float_as_uint(Wt[(k0 + lk + 4) * 72 + i0w + lrow + 8]);
            #pragma unroll
            for (int np = 0; np < 4; ++np) {
                int ncol = jbase + np * 8 + lrow;
                uint32_t b0 = __float_as_uint(Bt[(k0 + lk) * 72 + ncol]);
                uint32_t b1 = __float_as_uint(Bt[(k0 + lk + 4) * 72 + ncol]);
                mma_tf32(sf[np], a0, a1, a2, a3, b0, b1);
            }
        }
        __syncthreads();
    }

    const int cc0 = 2 * lk;
    #pragma unroll
    for (int rr = 0; rr < 2; ++rr) {
        int gm = m0 + i0w + lrow + rr * 8;
        float sc = 0.f, sh = 0.f;
        if (EPI == 2) {
            sc = g[gm] * rsqrtf(vv[gm] + EPS);
            sh = bb[gm] - mm[gm] * sc;
        }
        #pragma unroll
        for (int nt = 0; nt < 4; ++nt) {
            float e0 = sf[nt][rr * 2 + 0];
            float e1 = sf[nt][rr * 2 + 1];
            if (EPI == 2) {
                e0 = e0 * sc + sh; e1 = e1 * sc + sh;
                e0 = e0 / (1.f + __expf(-e0));
                e1 = e1 / (1.f + __expf(-e1));
            }
            size_t idx = (size_t)gm * HW + n0 + jbase + nt * 8 + cc0;
            *(float2*)&C[idx] = make_float2(e0, e1);
        }
    }
}

// ---------------- fused q/k/v/p projection (z selects weight; prefetch) ------
__global__ void __launch_bounds__(256) proj4(
    const float* __restrict__ x1,
    const float* __restrict__ wq, const float* __restrict__ bq,
    const float* __restrict__ wk, const float* __restrict__ bk,
    const float* __restrict__ wv, const float* __restrict__ bv,
    const float* __restrict__ wp, const float* __restrict__ bp,
    float* __restrict__ qf, __nv_bfloat16* __restrict__ qb,
    __nv_bfloat16* __restrict__ kb, __half* __restrict__ vh,
    float* __restrict__ pf)
{
    __shared__ float Wt[64 * 72];
    __shared__ float Bt[64 * 72];
    const int z = blockIdx.z;
    const float* A    = (z == 0) ? wq : (z == 1) ? wk : (z == 2) ? wv : wp;
    const float* bias = (z == 0) ? bq : (z == 1) ? bk : (z == 2) ? bv : bp;
    const int tid = threadIdx.x;
    const int wid = tid >> 5, lane = tid & 31;
    const int m0 = blockIdx.y * 64, n0 = blockIdx.x * 64;
    const int i0w = (wid & 3) * 16;
    const int jbase = (wid >> 2) * 32;
    const int lrow = lane >> 2, lk = lane & 3;
    const int mA = tid >> 2, kqA = (tid & 3) << 2;
    const int kkB = tid >> 4, n4B = (tid & 15) << 2;

    float sf[4][4];
    #pragma unroll
    for (int nt = 0; nt < 4; ++nt)
        #pragma unroll
        for (int e = 0; e < 4; ++e) sf[nt][e] = 0.f;

    float4 ar[4], br[4];
    #pragma unroll
    for (int i = 0; i < 4; ++i) {
        ar[i] = *(const float4*)&A[(size_t)(m0 + mA) * NC + kqA + 16 * i];
        br[i] = *(const float4*)&x1[(size_t)(kkB + 16 * i) * HW + n0 + n4B];
    }

    for (int kc = 0; kc < NC; kc += 64) {
        #pragma unroll
        for (int i = 0; i < 4; ++i) {
            int k4 = kqA + 16 * i;
            Wt[(k4 + 0) * 72 + mA] = tf32r(ar[i].x);
            Wt[(k4 + 1) * 72 + mA] = tf32r(ar[i].y);
            Wt[(k4 + 2) * 72 + mA] = tf32r(ar[i].z);
            Wt[(k4 + 3) * 72 + mA] = tf32r(ar[i].w);
            int kk = kkB + 16 * i;
            float* bp2 = &Bt[kk * 72 + n4B];
            bp2[0] = tf32r(br[i].x); bp2[1] = tf32r(br[i].y);
            bp2[2] = tf32r(br[i].z); bp2[3] = tf32r(br[i].w);
        }
        __syncthreads();
        if (kc + 64 < NC) {
            #pragma unroll
            for (int i = 0; i < 4; ++i) {
                ar[i] = *(const float4*)&A[(size_t)(m0 + mA) * NC + kc + 64 + kqA + 16 * i];
                br[i] = *(const float4*)&x1[(size_t)(kc + 64 + kkB + 16 * i) * HW + n0 + n4B];
            }
        }
        #pragma unroll
        for (int ks = 0; ks < 8; ++ks) {
            int k0 = ks * 8;
            uint32_t a0 = __float_as_uint(Wt[(k0 + lk) * 72 + i0w + lrow]);
            uint32_t a1 = __float_as_uint(Wt[(k0 + lk) * 72 + i0w + lrow + 8]);
            uint32_t a2 = __float_as_uint(Wt[(k0 + lk + 4) * 72 + i0w + lrow]);
            uint32_t a3 = __float_as_uint(Wt[(k0 + lk + 4) * 72 + i0w + lrow + 8]);
            #pragma unroll
            for (int np = 0; np < 4; ++np) {
                int ncol = jbase + np * 8 + lrow;
                uint32_t b0 = __float_as_uint(Bt[(k0 + lk) * 72 + ncol]);
                uint32_t b1 = __float_as_uint(Bt[(k0 + lk + 4) * 72 + ncol]);
                mma_tf32(sf[np], a0, a1, a2, a3, b0, b1);
            }
        }
        __syncthreads();
    }

    const int cc0 = 2 * lk;
    #pragma unroll
    for (int rr = 0; rr < 2; ++rr) {
        int gm = m0 + i0w + lrow + rr * 8;
        float bsv = bias[gm];
        #pragma unroll
        for (int nt = 0; nt < 4; ++nt) {
            float e0 = sf[nt][rr * 2 + 0] + bsv;
            float e1 = sf[nt][rr * 2 + 1] + bsv;
            size_t idx = (size_t)gm * HW + n0 + jbase + nt * 8 + cc0;
            if (z == 0) {
                *(float2*)&qf[idx] = make_float2(e0, e1);
                *(__nv_bfloat162*)&qb[idx] = __floats2bfloat162_rn(e0, e1);
            } else if (z == 1) {
                *(__nv_bfloat162*)&kb[idx] = __floats2bfloat162_rn(e0, e1);
            } else if (z == 2) {
                *(__half2*)&vh[idx] = __floats2half2_rn(e0, e1);
            } else {
                *(float2*)&pf[idx] = make_float2(e0, e1);
            }
        }
    }
}

// ---------------- stacked k-major GEMM (z=0: RW, z=1: AB; prefetch) ----------
__global__ void __launch_bounds__(256) krgemm(
    const float* __restrict__ lo0, const float* __restrict__ hi0,
    const float* __restrict__ B0, float* __restrict__ C0,
    const float* __restrict__ lo1, const float* __restrict__ hi1,
    const float* __restrict__ B1, float* __restrict__ C1)
{
    __shared__ float Wt[64 * 72];
    __shared__ float Bt[64 * 72];
    const int z = blockIdx.z;
    const float* a_lo = z ? lo1 : lo0;
    const float* a_hi = z ? hi1 : hi0;
    const float* B    = z ? B1  : B0;
    float*       C    = z ? C1  : C0;
    const int tid = threadIdx.x;
    const int wid = tid >> 5, lane = tid & 31;
    const int m0 = blockIdx.y * 64, n0 = blockIdx.x * 64;
    const int i0w = (wid & 3) * 16;
    const int jbase = (wid >> 2) * 32;
    const int lrow = lane >> 2, lk = lane & 3;
    const int M = 2 * NH;
    const int kkB = tid >> 4, n4B = (tid & 15) << 2;
    const int m4A = (tid & 15) << 2;
    const int gmA = m0 + m4A;

    float sf[4][4];
    #pragma unroll
    for (int nt = 0; nt < 4; ++nt)
        #pragma unroll
        for (int e = 0; e < 4; ++e) sf[nt][e] = 0.f;

    float4 ar[4], br[4];
    #pragma unroll
    for (int i = 0; i < 4; ++i) {
        int kk = kkB + 16 * i;
        float4 a4 = make_float4(0.f, 0.f, 0.f, 0.f);
        if (gmA < NH)          a4 = *(const float4*)&a_lo[(size_t)kk * NH + gmA];
        else if (gmA < 2 * NH) a4 = *(const float4*)&a_hi[(size_t)kk * NH + gmA - NH];
        ar[i] = a4;
        br[i] = *(const float4*)&B[(size_t)kk * HW + n0 + n4B];
    }

    for (int kc = 0; kc < NC; kc += 64) {
        #pragma unroll
        for (int i = 0; i < 4; ++i) {
            int kk = kkB + 16 * i;
            float* wp = &Wt[kk * 72 + m4A];
            wp[0] = tf32r(ar[i].x); wp[1] = tf32r(ar[i].y);
            wp[2] = tf32r(ar[i].z); wp[3] = tf32r(ar[i].w);
            float* bp = &Bt[kk * 72 + n4B];
            bp[0] = tf32r(br[i].x); bp[1] = tf32r(br[i].y);
            bp[2] = tf32r(br[i].z); bp[3] = tf32r(br[i].w);
        }
        __syncthreads();
        if (kc + 64 < NC) {
            #pragma unroll
            for (int i = 0; i < 4; ++i) {
                int kk = kc + 64 + kkB + 16 * i;
                float4 a4 = make_float4(0.f, 0.f, 0.f, 0.f);
                if (gmA < NH)          a4 = *(const float4*)&a_lo[(size_t)kk * NH + gmA];
                else if (gmA < 2 * NH) a4 = *(const float4*)&a_hi[(size_t)kk * NH + gmA - NH];
                ar[i] = a4;
                br[i] = *(const float4*)&B[(size_t)kk * HW + n0 + n4B];
            }
        }
        #pragma unroll
        for (int ks = 0; ks < 8; ++ks) {
            int k0 = ks * 8;
            uint32_t a0 = __float_as_uint(Wt[(k0 + lk) * 72 + i0w + lrow]);
            uint32_t a1 = __float_as_uint(Wt[(k0 + lk) * 72 + i0w + lrow + 8]);
            uint32_t a2 = __float_as_uint(Wt[(k0 + lk + 4) * 72 + i0w + lrow]);
            uint32_t a3 = __float_as_uint(Wt[(k0 + lk + 4) * 72 + i0w + lrow + 8]);
            #pragma unroll
            for (int np = 0; np < 4; ++np) {
                int ncol = jbase + np * 8 + lrow;
                uint32_t b0 = __float_as_uint(Bt[(k0 + lk) * 72 + ncol]);
                uint32_t b1 = __float_as_uint(Bt[(k0 + lk + 4) * 72 + ncol]);
                mma_tf32(sf[np], a0, a1, a2, a3, b0, b1);
            }
        }
        __syncthreads();
    }

    const int cc0 = 2 * lk;
    #pragma unroll
    for (int rr = 0; rr < 2; ++rr) {
        int gm = m0 + i0w + lrow + rr * 8;
        if (gm >= M) continue;
        #pragma unroll
        for (int nt = 0; nt < 4; ++nt) {
            size_t idx = (size_t)gm * HW + n0 + jbase + nt * 8 + cc0;
            *(float2*)&C[idx] = make_float2(sf[nt][rr * 2 + 0], sf[nt][rr * 2 + 1]);
        }
    }
}

// ---------------- expnorm: single-store softmax over 80 rows ------------------
__global__ void expnorm(const float* __restrict__ AB, float* __restrict__ PAB)
{
    int gid = blockIdx.x * blockDim.x + threadIdx.x;
    if (gid >= 2 * HW) return;
    int h = (gid >= HW) ? 1 : 0;
    int i = gid - h * HW;
    const float* src = AB  + (size_t)h * NH * HW;
    float*       dst = PAB + (size_t)h * NH * HW;
    float s = 0.f;
    #pragma unroll 8
    for (int t = 0; t < NH; ++t) s += __expf(src[t * HW + i]);
    float inv = 1.f / s;
    #pragma unroll 8
    for (int t = 0; t < NH; ++t)
        dst[t * HW + i] = __expf(src[t * HW + i]) * inv;
}

// ---------------- W3 = [w3@efh | w3@efw]  ([256][160], m-major) --------------
__global__ void __launch_bounds__(192) w3eff_kernel(
    const float* __restrict__ w3, const float* __restrict__ efh,
    const float* __restrict__ efw, float* __restrict__ W)
{
    __shared__ float sw3[NC];
    const int m = blockIdx.x;
    const int t = threadIdx.x;
    if (t < NC) sw3[t] = w3[(size_t)m * NC + t];
    __syncthreads();
    if (t >= 2 * NH) return;
    const float* ef = (t < NH) ? (efh + t) : (efw + t - NH);
    float sum = 0.f;
    #pragma unroll 16
    for (int c = 0; c < NC; ++c)
        sum += sw3[c] * ef[(size_t)c * NH];
    W[(size_t)m * 160 + t] = sum;
}

// ---------------- fused final (prefetched, dual source) ----------------------
__global__ void __launch_bounds__(256) final_gemm(
    const float* __restrict__ w2, const float* __restrict__ o1,
    const float* __restrict__ g2, const float* __restrict__ b2,
    const float* __restrict__ m2, const float* __restrict__ v2,
    const float* __restrict__ W3, const float* __restrict__ PAB,
    const float* __restrict__ g3, const float* __restrict__ b3,
    const float* __restrict__ m3, const float* __restrict__ v3,
    const float* __restrict__ x, float* __restrict__ out)
{
    __shared__ float Wt[64 * 72];
    __shared__ float Bt[64 * 72];
    const int tid = threadIdx.x;
    const int wid = tid >> 5, lane = tid & 31;
    const int m0 = blockIdx.y * 64, n0 = blockIdx.x * 64;
    const int i0w = (wid & 3) * 16;
    const int jbase = (wid >> 2) * 32;
    const int lrow = lane >> 2, lk = lane & 3;
    const int mA = tid >> 2, kqA = (tid & 3) << 2;
    const int kkB = tid >> 4, n4B = (tid & 15) << 2;

    float keep[4][4];
    float sf[4][4];
    #pragma unroll
    for (int nt = 0; nt < 4; ++nt)
        #pragma unroll
        for (int e = 0; e < 4; ++e) sf[nt][e] = 0.f;

    float4 ar[4], br[4];
    #pragma unroll
    for (int i = 0; i < 4; ++i) {
        ar[i] = *(const float4*)&w2[(size_t)(m0 + mA) * NC + kqA + 16 * i];
        br[i] = *(const float4*)&o1[(size_t)(kkB + 16 * i) * HW + n0 + n4B];
    }

    #pragma unroll
    for (int src = 0; src < 2; ++src) {
        const int Kp = src ? 160 : NC;
        for (int kc = 0; kc < Kp; kc += 64) {
            const int ck = (Kp - kc < 64) ? (Kp - kc) : 64;
            #pragma unroll
            for (int i = 0; i < 4; ++i) {
                int k4 = kqA + 16 * i;
                if (k4 < ck) {
                    Wt[(k4 + 0) * 72 + mA] = tf32r(ar[i].x);
                    Wt[(k4 + 1) * 72 + mA] = tf32r(ar[i].y);
                    Wt[(k4 + 2) * 72 + mA] = tf32r(ar[i].z);
                    Wt[(k4 + 3) * 72 + mA] = tf32r(ar[i].w);
                }
                int kk = kkB + 16 * i;
                if (kk < ck) {
                    float* bp = &Bt[kk * 72 + n4B];
                    bp[0] = tf32r(br[i].x); bp[1] = tf32r(br[i].y);
                    bp[2] = tf32r(br[i].z); bp[3] = tf32r(br[i].w);
                }
            }
            __syncthreads();
            {
                int srcN = src, kcN = kc + 64;
                if (kcN >= Kp) { srcN = src + 1; kcN = 0; }
                if (srcN < 2) {
                    const float* ApN = srcN ? W3 : w2;
                    const float* BpN = srcN ? PAB : o1;
                    int KpN = srcN ? 160 : NC;
                    int ckN = (KpN - kcN < 64) ? (KpN - kcN) : 64;
                    #pragma unroll
                    for (int i = 0; i < 4; ++i) {
                        int k4 = kqA + 16 * i;
                        if (k4 < ckN)
                            ar[i] = *(const float4*)&ApN[(size_t)(m0 + mA) * KpN + kcN + k4];
                        int kk = kkB + 16 * i;
                        if (kk < ckN)
                            br[i] = *(const float4*)&BpN[(size_t)(kcN + kk) * HW + n0 + n4B];
                    }
                }
            }
            const int nks = ck >> 3;
            for (int ks = 0; ks < nks; ++ks) {
                int k0 = ks * 8;
                uint32_t a0 = __float_as_uint(Wt[(k0 + lk) * 72 + i0w + lrow]);
                uint32_t a1 = __float_as_uint(Wt[(k0 + lk) * 72 + i0w + lrow + 8]);
                uint32_t a2 = __float_as_uint(Wt[(k0 + lk + 4) * 72 + i0w + lrow]);
                uint32_t a3 = __float_as_uint(Wt[(k0 + lk + 4) * 72 + i0w + lrow + 8]);
                #pragma unroll
                for (int np = 0; np < 4; ++np) {
                    int ncol = jbase + np * 8 + lrow;
                    uint32_t b0 = __float_as_uint(Bt[(k0 + lk) * 72 + ncol]);
                    uint32_t b1 = __float_as_uint(Bt[(k0 + lk + 4) * 72 + ncol]);
                    mma_tf32(sf[np], a0, a1, a2, a3, b0, b1);
                }
            }
            __syncthreads();
        }
        const float* gg  = src ? g3 : g2;
        const float* bbp = src ? b3 : b2;
        const float* mmp = src ? m3 : m2;
        const float* vvp = src ? v3 : v2;
        #pragma unroll
        for (int rr = 0; rr < 2; ++rr) {
            int gm = m0 + i0w + lrow + rr * 8;
            float sc = gg[gm] * rsqrtf(vvp[gm] + EPS);
            float sh = bbp[gm] - mmp[gm] * sc;
            #pragma unroll
            for (int nt = 0; nt < 4; ++nt) {
                #pragma unroll
                for (int e2 = 0; e2 < 2; ++e2) {
                    float val = sf[nt][rr * 2 + e2] * sc + sh;
                    val = val / (1.f + __expf(-val));
                    if (src == 0) { keep[nt][rr * 2 + e2] = val; sf[nt][rr * 2 + e2] = 0.f; }
                    else          { keep[nt][rr * 2 + e2] += val; }
                }
            }
        }
    }

    const int cc0 = 2 * lk;
    #pragma unroll
    for (int rr = 0; rr < 2; ++rr) {
        int gm = m0 + i0w + lrow + rr * 8;
        #pragma unroll
        for (int nt = 0; nt < 4; ++nt) {
            size_t idx = (size_t)gm * HW + n0 + jbase + nt * 8 + cc0;
            float2 x2 = *(const float2*)&x[idx];
            *(float2*)&out[idx] = make_float2(keep[nt][rr * 2 + 0] + x2.x,
                                              keep[nt][rr * 2 + 1] + x2.y);
        }
    }
}

// ---------------- branch-1 flash attention: 4 fat warps, Q + softmax in regs --
#define QS_OFF   0               // bf16 [128][72]
#define KS_OFF   18432           // bf16 [128][72]
#define VS_OFF   36864           // f16  [128][72]
#define RB_OFF   55296           // f16  [64][72] fused Rw+Rh bias
#define FL_SM_BYTES 64512

__global__ void __launch_bounds__(128, 2) flash_kernel(
    const __nv_bfloat16* __restrict__ q, const __nv_bfloat16* __restrict__ k,
    const __half* __restrict__ v, const float* __restrict__ Rh,
    const float* __restrict__ Rw, float* __restrict__ op,
    float* __restrict__ mp, float* __restrict__ lp)
{
    extern __shared__ char smc[];
    __half* RbH = (__half*)(smc + RB_OFF);

    const int tid  = threadIdx.x;
    const int wid  = tid >> 5, lane = tid & 31;
    const int lr   = lane & 7, gq = lane >> 3;
    const int lrowq = lane >> 2, lk = lane & 3;
    const int i0   = blockIdx.x * 64;
    const int spl  = blockIdx.y;
    const int t0   = (spl * 100) / SPLIT;
    const int t1   = ((spl + 1) * 100) / SPLIT;
    const int i0w  = wid * 16;
    const float L2E = 1.4426950408889634f;

    const uint32_t qsb = (uint32_t)__cvta_generic_to_shared(smc + QS_OFF);
    const uint32_t ksb = (uint32_t)__cvta_generic_to_shared(smc + KS_OFF);
    const uint32_t vsb = (uint32_t)__cvta_generic_to_shared(smc + VS_OFF);

    // prologue: Q, K(t0), V(t0) via cp.async (3 groups)
    {
        #pragma unroll
        for (int it = 0; it < 8; ++it) {
            int ch = tid + it * 128;
            int c = ch >> 3, j8 = (ch & 7) * 8;
            cpa16(qsb + (uint32_t)((c * 72 + j8) * 2), &q[(size_t)c * HW + i0 + j8]);
        }
        CPA_COMMIT();
        int j0n = t0 * 64;
        #pragma unroll
        for (int it = 0; it < 8; ++it) {
            int ch = tid + it * 128;
            int c = ch >> 3, j8 = (ch & 7) * 8;
            cpa16(ksb + (uint32_t)((c * 72 + j8) * 2), &k[(size_t)c * HW + j0n + j8]);
        }
        CPA_COMMIT();
        #pragma unroll
        for (int it = 0; it < 8; ++it) {
            int ch = tid + it * 128;
            int c = ch >> 3, j8 = (ch & 7) * 8;
            cpa16(vsb + (uint32_t)((c * 72 + j8) * 2), &v[(size_t)c * HW + j0n + j8]);
        }
        CPA_COMMIT();
    }
    asm volatile("cp.async.wait_group 2;");   // Q landed
    __syncthreads();

    // hoist Q fragments (loop-invariant): 8 k-steps x 4 regs
    uint32_t qf[8][4];
    #pragma unroll
    for (int ks = 0; ks < 8; ++ks)
        ldsm4t(qf[ks][0], qf[ks][1], qf[ks][2], qf[ks][3],
               qsb + (uint32_t)(((ks * 16 + lr + (gq >> 1) * 8) * 72
                                + i0w + (gq & 1) * 8) * 2));

    float d[16][4];
    #pragma unroll
    for (int nt = 0; nt < 16; ++nt)
        #pragma unroll
        for (int e = 0; e < 4; ++e) d[nt][e] = 0.f;
    float m0v = -1e30f, m1v = -1e30f, l0v = 0.f, l1v = 0.f;
    const int r0 = i0w + lrowq, r1 = r0 + 8;

    for (int t = t0; t < t1; ++t) {
        const int j0 = t * 64;
        const bool more = (t + 1 < t1);

        // stage fused bias tile fp16 (safe: previous softmax done at sync C)
        #pragma unroll
        for (int e = 0; e < 8; ++e) {
            int ee = tid + e * 128;
            int row = ee >> 4, c4 = (ee & 15) << 2;
            int gi = i0 + row;
            float4 a = *(const float4*)&Rw[(gi % 80) * HW + j0 + c4];
            float4 b = *(const float4*)&Rh[(gi / 80) * HW + j0 + c4];
            __half2* dst = (__half2*)&RbH[row * 72 + c4];
            dst[0] = __floats2half2_rn(a.x + b.x, a.y + b.y);
            dst[1] = __floats2half2_rn(a.z + b.z, a.w + b.w);
        }
        asm volatile("cp.async.wait_group 1;");   // K(t) landed
        __syncthreads();                          // A: K + bias visible

        // ---- QK^T (bf16), full 64 j per warp ----
        float sf[8][4];
        #pragma unroll
        for (int nb = 0; nb < 8; ++nb)
            #pragma unroll
            for (int e = 0; e < 4; ++e) sf[nb][e] = 0.f;

        #pragma unroll
        for (int ks = 0; ks < 8; ++ks) {
            #pragma unroll
            for (int jn = 0; jn < 4; ++jn) {
                uint32_t b0, b1, b2, b3;
                ldsm4t(b0, b1, b2, b3,
                       ksb + (uint32_t)(((ks * 16 + lr + (gq & 1) * 8) * 72
                                        + jn * 16 + (gq >> 1) * 8) * 2));
                mma_bf16(sf[jn * 2],     qf[ks][0], qf[ks][1], qf[ks][2], qf[ks][3], b0, b1);
                mma_bf16(sf[jn * 2 + 1], qf[ks][0], qf[ks][1], qf[ks][2], qf[ks][3], b2, b3);
            }
        }
        asm volatile("cp.async.wait_group 0;");   // V(t) landed
        __syncthreads();                          // B: Ks free, Vs visible

        if (more) {                               // K(t+1) in place
            int j0n = (t + 1) * 64;
            #pragma unroll
            for (int it = 0; it < 8; ++it) {
                int ch = tid + it * 128;
                int c = ch >> 3, j8 = (ch & 7) * 8;
                cpa16(ksb + (uint32_t)((c * 72 + j8) * 2), &k[(size_t)c * HW + j0n + j8]);
            }
            CPA_COMMIT();
        }

        // ---- softmax entirely warp-local (regs + quad shfl) ----
        #pragma unroll
        for (int nb = 0; nb < 8; ++nb) {
            int col = nb * 8 + 2 * lk;
            float2 b0 = __half22float2(*(__half2*)&RbH[r0 * 72 + col]);
            float2 b1 = __half22float2(*(__half2*)&RbH[r1 * 72 + col]);
            sf[nb][0] += b0.x; sf[nb][1] += b0.y;
            sf[nb][2] += b1.x; sf[nb][3] += b1.y;
        }
        float mx0 = -1e30f, mx1 = -1e30f;
        #pragma unroll
        for (int nb = 0; nb < 8; ++nb) {
            mx0 = fmaxf(mx0, fmaxf(sf[nb][0], sf[nb][1]));
            mx1 = fmaxf(mx1, fmaxf(sf[nb][2], sf[nb][3]));
        }
        mx0 = fmaxf(mx0, __shfl_xor_sync(0xffffffffu, mx0, 1));
        mx0 = fmaxf(mx0, __shfl_xor_sync(0xffffffffu, mx0, 2));
        mx1 = fmaxf(mx1, __shfl_xor_sync(0xffffffffu, mx1, 1));
        mx1 = fmaxf(mx1, __shfl_xor_sync(0xffffffffu, mx1, 2));
        float nm0 = fmaxf(m0v, mx0), nm1 = fmaxf(m1v, mx1);
        float f0 = exp2f((m0v - nm0) * L2E);
        float f1 = exp2f((m1v - nm1) * L2E);
        uint32_t ph[8][2];
        float s0 = 0.f, s1 = 0.f;
        #pragma unroll
        for (int nb = 0; nb < 8; ++nb) {
            float u0 = (sf[nb][0] - nm0) * L2E, u1 = (sf[nb][1] - nm0) * L2E;
            float u2 = (sf[nb][2] - nm1) * L2E, u3 = (sf[nb][3] - nm1) * L2E;
            uint32_t p0, p1;
            asm("cvt.rn.f16x2.f32 %0, %1, %2;" : "=r"(p0) : "f"(u1), "f"(u0));
            asm("ex2.approx.f16x2 %0, %0;" : "+r"(p0));
            asm("cvt.rn.f16x2.f32 %0, %1, %2;" : "=r"(p1) : "f"(u3), "f"(u2));
            asm("ex2.approx.f16x2 %0, %0;" : "+r"(p1));
            ph[nb][0] = p0; ph[nb][1] = p1;
            float2 e0 = __half22float2(*reinterpret_cast<__half2*>(&p0));
            float2 e1 = __half22float2(*reinterpret_cast<__half2*>(&p1));
            s0 += e0.x + e0.y;
            s1 += e1.x + e1.y;
        }
        s0 += __shfl_xor_sync(0xffffffffu, s0, 1);
        s0 += __shfl_xor_sync(0xffffffffu, s0, 2);
        s1 += __shfl_xor_sync(0xffffffffu, s1, 1);
        s1 += __shfl_xor_sync(0xffffffffu, s1, 2);
        l0v = l0v * f0 + s0;  m0v = nm0;
        l1v = l1v * f1 + s1;  m1v = nm1;
        #pragma unroll
        for (int nt = 0; nt < 16; ++nt) {
            d[nt][0] *= f0; d[nt][1] *= f0;
            d[nt][2] *= f1; d[nt][3] *= f1;
        }

        // ---- P @ V^T (fp16): A = register P frags, k = 64 j, n = 128 c ----
        #pragma unroll
        for (int ks = 0; ks < 4; ++ks) {
            uint32_t a0 = ph[2 * ks][0], a1 = ph[2 * ks][1];
            uint32_t a2 = ph[2 * ks + 1][0], a3 = ph[2 * ks + 1][1];
            #pragma unroll
            for (int np = 0; np < 8; ++np) {
                uint32_t b0, b1, b2, b3;
                ldsm4(b0, b1, b2, b3,
                      vsb + (uint32_t)(((np * 16 + lr + (gq >> 1) * 8) * 72
                                       + ks * 16 + (gq & 1) * 8) * 2));
                mma_f16(d[np * 2],     a0, a1, a2, a3, b0, b1);
                mma_f16(d[np * 2 + 1], a0, a1, a2, a3, b2, b3);
            }
        }
        __syncthreads();                          // C: Vs free, bias free

        if (more) {                               // V(t+1)
            int j0n = (t + 1) * 64;
            #pragma unroll
            for (int it = 0; it < 8; ++it) {
                int ch = tid + it * 128;
                int c = ch >> 3, j8 = (ch & 7) * 8;
                cpa16(vsb + (uint32_t)((c * 72 + j8) * 2), &v[(size_t)c * HW + j0n + j8]);
            }
            CPA_COMMIT();
        }
    }

    // ---- epilogue: warp owns 16 rows x all 128 channels; direct writes ----
    #pragma unroll
    for (int nt = 0; nt < 16; ++nt) {
        int c = nt * 8 + 2 * lk;
        op[(size_t)(spl * NC + c)     * HW + i0 + r0] = d[nt][0];
        op[(size_t)(spl * NC + c + 1) * HW + i0 + r0] = d[nt][1];
        op[(size_t)(spl * NC + c)     * HW + i0 + r1] = d[nt][2];
        op[(size_t)(spl * NC + c + 1) * HW + i0 + r1] = d[nt][3];
    }
    if (lk == 0) {
        mp[spl * HW + i0 + r0] = m0v;
        mp[spl * HW + i0 + r1] = m1v;
        lp[spl * HW + i0 + r0] = l0v;
        lp[spl * HW + i0 + r1] = l1v;
    }
}

// ---------------- split-j combine (channel-parallel) -------------------------
__global__ void combine_kernel(const float* __restrict__ op,
                               const float* __restrict__ mp,
                               const float* __restrict__ lp,
                               float* __restrict__ out1)
{
    int i = blockIdx.x * blockDim.x + threadIdx.x;
    if (i >= HW) return;
    int c0 = blockIdx.y * 8;
    float m[SPLIT], w[SPLIT];
    float M = -1e30f;
    #pragma unroll
    for (int s = 0; s < SPLIT; ++s) { m[s] = mp[s * HW + i]; M = fmaxf(M, m[s]); }
    float L = 0.f;
    #pragma unroll
    for (int s = 0; s < SPLIT; ++s) { w[s] = __expf(m[s] - M); L += lp[s * HW + i] * w[s]; }
    float inv = 1.f / L;
    for (int c = c0; c < c0 + 8; ++c) {
        float acc = 0.f;
        #pragma unroll
        for (int s = 0; s < SPLIT; ++s)
            acc += op[((size_t)(s * NC + c)) * HW + i] * w[s];
        out1[(size_t)c * HW + i] = acc * inv;
    }
}

// -------------------------------- launch -------------------------------------
extern "C" void kernel_launch(void* const* d_in, const int* in_sizes, int n_in,
                              void* d_out, int out_size)
{
    (void)in_sizes; (void)n_in; (void)out_size;
    const float* x    = (const float*)d_in[0];
    const float* w1   = (const float*)d_in[1];
    const float* g1   = (const float*)d_in[2];
    const float* b1   = (const float*)d_in[3];
    const float* m1   = (const float*)d_in[4];
    const float* v1   = (const float*)d_in[5];
    const float* w2   = (const float*)d_in[6];
    const float* g2   = (const float*)d_in[7];
    const float* b2   = (const float*)d_in[8];
    const float* m2   = (const float*)d_in[9];
    const float* v2   = (const float*)d_in[10];
    const float* w3   = (const float*)d_in[11];
    const float* g3   = (const float*)d_in[12];
    const float* b3   = (const float*)d_in[13];
    const float* m3   = (const float*)d_in[14];
    const float* v3   = (const float*)d_in[15];
    const float* wq   = (const float*)d_in[16];
    const float* bq   = (const float*)d_in[17];
    const float* wk   = (const float*)d_in[18];
    const float* bk   = (const float*)d_in[19];
    const float* wv   = (const float*)d_in[20];
    const float* bv   = (const float*)d_in[21];
    const float* wp   = (const float*)d_in[22];
    const float* bp   = (const float*)d_in[23];
    const float* relh = (const float*)d_in[24];
    const float* relw = (const float*)d_in[25];
    const float* efh  = (const float*)d_in[26];
    const float* efw  = (const float*)d_in[27];
    float* out = (float*)d_out;

    float *px1, *pq, *pp, *pRW, *pAB, *pPAB, *pW3, *po1, *pop, *pmp, *plp;
    __nv_bfloat16 *pqb, *pkb;
    __half *pvh;
    cudaGetSymbolAddress((void**)&px1, d_x1);
    cudaGetSymbolAddress((void**)&pq,  d_q);
    cudaGetSymbolAddress((void**)&pp,  d_p);
    cudaGetSymbolAddress((void**)&pqb, d_qb);
    cudaGetSymbolAddress((void**)&pkb, d_kb);
    cudaGetSymbolAddress((void**)&pvh, d_vh);
    cudaGetSymbolAddress((void**)&pRW, d_RW);
    cudaGetSymbolAddress((void**)&pAB, d_AB);
    cudaGetSymbolAddress((void**)&pPAB, d_PAB);
    cudaGetSymbolAddress((void**)&pW3, d_W3);
    cudaGetSymbolAddress((void**)&po1, d_o1);
    cudaGetSymbolAddress((void**)&pop, d_op);
    cudaGetSymbolAddress((void**)&pmp, d_mp);
    cudaGetSymbolAddress((void**)&plp, d_lp);

    cudaFuncSetAttribute(flash_kernel,
        cudaFuncAttributeMaxDynamicSharedMemorySize, FL_SM_BYTES);

    dim3 g100_2(100, 2), g100_4(100, 4);
    dim3 gproj(100, 2, 4), gkr(100, 3, 2), gfl(100, SPLIT), gcmb(25, 16);

    // [0] W3 = [w3@efh | w3@efw]
    w3eff_kernel<<<ND, 192>>>(w3, efh, efw, pW3);
    // [1] x1 = SiLU(BN(w1 @ x))
    tgemm<2><<<g100_2, 256>>>(w1, x, px1, NC, ND, g1, b1, m1, v1);
    // [2] fused q/k/v/p projections (fp32 q,p; bf16 q,k; fp16 v)
    proj4<<<gproj, 256>>>(px1, wq, bq, wk, bk, wv, bv, wp, bp,
        pq, pqb, pkb, pvh, pp);
    // [3] z=0: [Rh;Rw] = [rel_h;rel_w]^T q;  z=1: [ABh;ABw] = [ef_h;ef_w]^T p
    krgemm<<<gkr, 256>>>(relh, relw, pq, pRW, efh, efw, pp, pAB);
    // [4] PAB = per-column softmax of both halves (single-store)
    expnorm<<<50, 256>>>(pAB, pPAB);
    // [5] flash attention (4 fat warps, Q-frags + softmax in registers)
    flash_kernel<<<gfl, 128, FL_SM_BYTES>>>(pqb, pkb, pvh,
        pRW, pRW + NH * HW, pop, pmp, plp);
    // [6] combine split partials -> out1
    combine_kernel<<<gcmb, 256>>>(pop, pmp, plp, po1);
    // [7] out = x + SiLU(BN2(w2@o1)) + SiLU(BN3(W3@PAB))
    final_gemm<<<g100_4, 256>>>(w2, po1, g2, b2, m2, v2,
        pW3, pPAB, g3, b3, m3, v3, x, out);
}

// round 17
// speedup vs baseline: 1.5529x; 1.0350x over previous
#include <cuda_runtime.h>
#include <cuda_bf16.h>
#include <cuda_fp16.h>
#include <cstdint>

#define EPS 1e-5f
#define HW 6400
#define NC 128
#define ND 256
#define NH 80
#define SPLIT 8

// ---------------- tensor-core helpers ----------------------------------------
__device__ __forceinline__ void ldsm4(uint32_t& r0, uint32_t& r1,
                                      uint32_t& r2, uint32_t& r3, uint32_t a) {
    asm volatile("ldmatrix.sync.aligned.m8n8.x4.shared.b16 {%0,%1,%2,%3},[%4];"
        : "=r"(r0), "=r"(r1), "=r"(r2), "=r"(r3) : "r"(a));
}
__device__ __forceinline__ void ldsm4t(uint32_t& r0, uint32_t& r1,
                                       uint32_t& r2, uint32_t& r3, uint32_t a) {
    asm volatile("ldmatrix.sync.aligned.m8n8.x4.trans.shared.b16 {%0,%1,%2,%3},[%4];"
        : "=r"(r0), "=r"(r1), "=r"(r2), "=r"(r3) : "r"(a));
}
__device__ __forceinline__ void mma_bf16(float* d, uint32_t a0, uint32_t a1,
                                         uint32_t a2, uint32_t a3,
                                         uint32_t b0, uint32_t b1) {
    asm volatile("mma.sync.aligned.m16n8k16.row.col.f32.bf16.bf16.f32 "
        "{%0,%1,%2,%3},{%4,%5,%6,%7},{%8,%9},{%0,%1,%2,%3};"
        : "+f"(d[0]), "+f"(d[1]), "+f"(d[2]), "+f"(d[3])
        : "r"(a0), "r"(a1), "r"(a2), "r"(a3), "r"(b0), "r"(b1));
}
__device__ __forceinline__ void mma_f16(float* d, uint32_t a0, uint32_t a1,
                                        uint32_t a2, uint32_t a3,
                                        uint32_t b0, uint32_t b1) {
    asm volatile("mma.sync.aligned.m16n8k16.row.col.f32.f16.f16.f32 "
        "{%0,%1,%2,%3},{%4,%5,%6,%7},{%8,%9},{%0,%1,%2,%3};"
        : "+f"(d[0]), "+f"(d[1]), "+f"(d[2]), "+f"(d[3])
        : "r"(a0), "r"(a1), "r"(a2), "r"(a3), "r"(b0), "r"(b1));
}
__device__ __forceinline__ void mma_tf32(float* d, uint32_t a0, uint32_t a1,
                                         uint32_t a2, uint32_t a3,
                                         uint32_t b0, uint32_t b1) {
    asm volatile("mma.sync.aligned.m16n8k8.row.col.f32.tf32.tf32.f32 "
        "{%0,%1,%2,%3},{%4,%5,%6,%7},{%8,%9},{%0,%1,%2,%3};"
        : "+f"(d[0]), "+f"(d[1]), "+f"(d[2]), "+f"(d[3])
        : "r"(a0), "r"(a1), "r"(a2), "r"(a3), "r"(b0), "r"(b1));
}
__device__ __forceinline__ float tf32r(float x) {
    uint32_t r;
    asm("cvt.rna.tf32.f32 %0, %1;" : "=r"(r) : "f"(x));
    return __uint_as_float(r);
}
__device__ __forceinline__ void cpa16(uint32_t s, const void* g) {
    asm volatile("cp.async.cg.shared.global [%0], [%1], 16;" :: "r"(s), "l"(g));
}
#define CPA_COMMIT() asm volatile("cp.async.commit_group;")

// ---------------- scratch (static device globals; no allocation) -------------
__device__ float d_x1 [NC*HW];
__device__ float d_q  [NC*HW];
__device__ float d_p  [NC*HW];
__device__ __nv_bfloat16 d_qb[NC*HW];
__device__ __nv_bfloat16 d_kb[NC*HW];
__device__ __half d_vh[NC*HW];
__device__ float d_RW  [2*NH*HW];   // [Rh(80); Rw(80)]
__device__ float d_AB  [2*NH*HW];   // [ABh(80); ABw(80)]
__device__ float d_PAB [2*NH*HW];   // normalized [PA(80); PB(80)]
__device__ float d_W3  [ND*2*NH];   // [w3@efh | w3@efw]  m-major [256][160]
__device__ float d_o1  [NC*HW];
__device__ float d_op  [SPLIT*NC*HW];
__device__ float d_mp  [SPLIT*HW];
__device__ float d_lp  [SPLIT*HW];

// ---------------- tf32 GEMM (x1 conv) with register-prefetch pipeline --------
template<int EPI>
__global__ void __launch_bounds__(256) tgemm(
    const float* __restrict__ A, const float* __restrict__ B,
    float* __restrict__ C, int M, int K,
    const float* __restrict__ g, const float* __restrict__ bb,
    const float* __restrict__ mm, const float* __restrict__ vv)
{
    __shared__ float Wt[64 * 72];
    __shared__ float Bt[64 * 72];
    const int tid = threadIdx.x;
    const int wid = tid >> 5, lane = tid & 31;
    const int m0 = blockIdx.y * 64, n0 = blockIdx.x * 64;
    const int i0w = (wid & 3) * 16;
    const int jbase = (wid >> 2) * 32;
    const int lrow = lane >> 2, lk = lane & 3;
    const int mA = tid >> 2, kqA = (tid & 3) << 2;
    const int kkB = tid >> 4, n4B = (tid & 15) << 2;

    float sf[4][4];
    #pragma unroll
    for (int nt = 0; nt < 4; ++nt)
        #pragma unroll
        for (int e = 0; e < 4; ++e) sf[nt][e] = 0.f;

    float4 ar[4], br[4];
    #pragma unroll
    for (int i = 0; i < 4; ++i) {
        ar[i] = *(const float4*)&A[(size_t)(m0 + mA) * K + kqA + 16 * i];
        br[i] = *(const float4*)&B[(size_t)(kkB + 16 * i) * HW + n0 + n4B];
    }

    for (int kc = 0; kc < K; kc += 64) {
        #pragma unroll
        for (int i = 0; i < 4; ++i) {
            int k4 = kqA + 16 * i;
            Wt[(k4 + 0) * 72 + mA] = tf32r(ar[i].x);
            Wt[(k4 + 1) * 72 + mA] = tf32r(ar[i].y);
            Wt[(k4 + 2) * 72 + mA] = tf32r(ar[i].z);
            Wt[(k4 + 3) * 72 + mA] = tf32r(ar[i].w);
            int kk = kkB + 16 * i;
            float* bp = &Bt[kk * 72 + n4B];
            bp[0] = tf32r(br[i].x); bp[1] = tf32r(br[i].y);
            bp[2] = tf32r(br[i].z); bp[3] = tf32r(br[i].w);
        }
        __syncthreads();
        if (kc + 64 < K) {
            #pragma unroll
            for (int i = 0; i < 4; ++i) {
                ar[i] = *(const float4*)&A[(size_t)(m0 + mA) * K + kc + 64 + kqA + 16 * i];
                br[i] = *(const float4*)&B[(size_t)(kc + 64 + kkB + 16 * i) * HW + n0 + n4B];
            }
        }
        #pragma unroll
        for (int ks = 0; ks < 8; ++ks) {
            int k0 = ks * 8;
            uint32_t a0 = __float_as_uint(Wt[(k0 + lk) * 72 + i0w + lrow]);
            uint32_t a1 = __float_as_uint(Wt[(k0 + lk) * 72 + i0w + lrow + 8]);
            uint32_t a2 = __float_as_uint(Wt[(k0 + lk + 4) * 72 + i0w + lrow]);
            uint32_t a3 = __float_as_uint(Wt[(k0 + lk + 4) * 72 + i0w + lrow + 8]);
            #pragma unroll
            for (int np = 0; np < 4; ++np) {
                int ncol = jbase + np * 8 + lrow;
                uint32_t b0 = __float_as_uint(Bt[(k0 + lk) * 72 + ncol]);
                uint32_t b1 = __float_as_uint(Bt[(k0 + lk + 4) * 72 + ncol]);
                mma_tf32(sf[np], a0, a1, a2, a3, b0, b1);
            }
        }
        __syncthreads();
    }

    const int cc0 = 2 * lk;
    #pragma unroll
    for (int rr = 0; rr < 2; ++rr) {
        int gm = m0 + i0w + lrow + rr * 8;
        float sc = 0.f, sh = 0.f;
        if (EPI == 2) {
            sc = g[gm] * rsqrtf(vv[gm] + EPS);
            sh = bb[gm] - mm[gm] * sc;
        }
        #pragma unroll
        for (int nt = 0; nt < 4; ++nt) {
            float e0 = sf[nt][rr * 2 + 0];
            float e1 = sf[nt][rr * 2 + 1];
            if (EPI == 2) {
                e0 = e0 * sc + sh; e1 = e1 * sc + sh;
                e0 = e0 / (1.f + __expf(-e0));
                e1 = e1 / (1.f + __expf(-e1));
            }
            size_t idx = (size_t)gm * HW + n0 + jbase + nt * 8 + cc0;
            *(float2*)&C[idx] = make_float2(e0, e1);
        }
    }
}

// ---------------- fused q/k/v/p projection (z selects weight; prefetch) ------
__global__ void __launch_bounds__(256) proj4(
    const float* __restrict__ x1,
    const float* __restrict__ wq, const float* __restrict__ bq,
    const float* __restrict__ wk, const float* __restrict__ bk,
    const float* __restrict__ wv, const float* __restrict__ bv,
    const float* __restrict__ wp, const float* __restrict__ bp,
    float* __restrict__ qf, __nv_bfloat16* __restrict__ qb,
    __nv_bfloat16* __restrict__ kb, __half* __restrict__ vh,
    float* __restrict__ pf)
{
    __shared__ float Wt[64 * 72];
    __shared__ float Bt[64 * 72];
    const int z = blockIdx.z;
    const float* A    = (z == 0) ? wq : (z == 1) ? wk : (z == 2) ? wv : wp;
    const float* bias = (z == 0) ? bq : (z == 1) ? bk : (z == 2) ? bv : bp;
    const int tid = threadIdx.x;
    const int wid = tid >> 5, lane = tid & 31;
    const int m0 = blockIdx.y * 64, n0 = blockIdx.x * 64;
    const int i0w = (wid & 3) * 16;
    const int jbase = (wid >> 2) * 32;
    const int lrow = lane >> 2, lk = lane & 3;
    const int mA = tid >> 2, kqA = (tid & 3) << 2;
    const int kkB = tid >> 4, n4B = (tid & 15) << 2;

    float sf[4][4];
    #pragma unroll
    for (int nt = 0; nt < 4; ++nt)
        #pragma unroll
        for (int e = 0; e < 4; ++e) sf[nt][e] = 0.f;

    float4 ar[4], br[4];
    #pragma unroll
    for (int i = 0; i < 4; ++i) {
        ar[i] = *(const float4*)&A[(size_t)(m0 + mA) * NC + kqA + 16 * i];
        br[i] = *(const float4*)&x1[(size_t)(kkB + 16 * i) * HW + n0 + n4B];
    }

    for (int kc = 0; kc < NC; kc += 64) {
        #pragma unroll
        for (int i = 0; i < 4; ++i) {
            int k4 = kqA + 16 * i;
            Wt[(k4 + 0) * 72 + mA] = tf32r(ar[i].x);
            Wt[(k4 + 1) * 72 + mA] = tf32r(ar[i].y);
            Wt[(k4 + 2) * 72 + mA] = tf32r(ar[i].z);
            Wt[(k4 + 3) * 72 + mA] = tf32r(ar[i].w);
            int kk = kkB + 16 * i;
            float* bp2 = &Bt[kk * 72 + n4B];
            bp2[0] = tf32r(br[i].x); bp2[1] = tf32r(br[i].y);
            bp2[2] = tf32r(br[i].z); bp2[3] = tf32r(br[i].w);
        }
        __syncthreads();
        if (kc + 64 < NC) {
            #pragma unroll
            for (int i = 0; i < 4; ++i) {
                ar[i] = *(const float4*)&A[(size_t)(m0 + mA) * NC + kc + 64 + kqA + 16 * i];
                br[i] = *(const float4*)&x1[(size_t)(kc + 64 + kkB + 16 * i) * HW + n0 + n4B];
            }
        }
        #pragma unroll
        for (int ks = 0; ks < 8; ++ks) {
            int k0 = ks * 8;
            uint32_t a0 = __float_as_uint(Wt[(k0 + lk) * 72 + i0w + lrow]);
            uint32_t a1 = __float_as_uint(Wt[(k0 + lk) * 72 + i0w + lrow + 8]);
            uint32_t a2 = __float_as_uint(Wt[(k0 + lk + 4) * 72 + i0w + lrow]);
            uint32_t a3 = __float_as_uint(Wt[(k0 + lk + 4) * 72 + i0w + lrow + 8]);
            #pragma unroll
            for (int np = 0; np < 4; ++np) {
                int ncol = jbase + np * 8 + lrow;
                uint32_t b0 = __float_as_uint(Bt[(k0 + lk) * 72 + ncol]);
                uint32_t b1 = __float_as_uint(Bt[(k0 + lk + 4) * 72 + ncol]);
                mma_tf32(sf[np], a0, a1, a2, a3, b0, b1);
            }
        }
        __syncthreads();
    }

    const int cc0 = 2 * lk;
    #pragma unroll
    for (int rr = 0; rr < 2; ++rr) {
        int gm = m0 + i0w + lrow + rr * 8;
        float bsv = bias[gm];
        #pragma unroll
        for (int nt = 0; nt < 4; ++nt) {
            float e0 = sf[nt][rr * 2 + 0] + bsv;
            float e1 = sf[nt][rr * 2 + 1] + bsv;
            size_t idx = (size_t)gm * HW + n0 + jbase + nt * 8 + cc0;
            if (z == 0) {
                *(float2*)&qf[idx] = make_float2(e0, e1);
                *(__nv_bfloat162*)&qb[idx] = __floats2bfloat162_rn(e0, e1);
            } else if (z == 1) {
                *(__nv_bfloat162*)&kb[idx] = __floats2bfloat162_rn(e0, e1);
            } else if (z == 2) {
                *(__half2*)&vh[idx] = __floats2half2_rn(e0, e1);
            } else {
                *(float2*)&pf[idx] = make_float2(e0, e1);
            }
        }
    }
}

// ---------------- stacked k-major GEMM (z=0: RW, z=1: AB; prefetch) ----------
__global__ void __launch_bounds__(256) krgemm(
    const float* __restrict__ lo0, const float* __restrict__ hi0,
    const float* __restrict__ B0, float* __restrict__ C0,
    const float* __restrict__ lo1, const float* __restrict__ hi1,
    const float* __restrict__ B1, float* __restrict__ C1)
{
    __shared__ float Wt[64 * 72];
    __shared__ float Bt[64 * 72];
    const int z = blockIdx.z;
    const float* a_lo = z ? lo1 : lo0;
    const float* a_hi = z ? hi1 : hi0;
    const float* B    = z ? B1  : B0;
    float*       C    = z ? C1  : C0;
    const int tid = threadIdx.x;
    const int wid = tid >> 5, lane = tid & 31;
    const int m0 = blockIdx.y * 64, n0 = blockIdx.x * 64;
    const int i0w = (wid & 3) * 16;
    const int jbase = (wid >> 2) * 32;
    const int lrow = lane >> 2, lk = lane & 3;
    const int M = 2 * NH;
    const int kkB = tid >> 4, n4B = (tid & 15) << 2;
    const int m4A = (tid & 15) << 2;
    const int gmA = m0 + m4A;

    float sf[4][4];
    #pragma unroll
    for (int nt = 0; nt < 4; ++nt)
        #pragma unroll
        for (int e = 0; e < 4; ++e) sf[nt][e] = 0.f;

    float4 ar[4], br[4];
    #pragma unroll
    for (int i = 0; i < 4; ++i) {
        int kk = kkB + 16 * i;
        float4 a4 = make_float4(0.f, 0.f, 0.f, 0.f);
        if (gmA < NH)          a4 = *(const float4*)&a_lo[(size_t)kk * NH + gmA];
        else if (gmA < 2 * NH) a4 = *(const float4*)&a_hi[(size_t)kk * NH + gmA - NH];
        ar[i] = a4;
        br[i] = *(const float4*)&B[(size_t)kk * HW + n0 + n4B];
    }

    for (int kc = 0; kc < NC; kc += 64) {
        #pragma unroll
        for (int i = 0; i < 4; ++i) {
            int kk = kkB + 16 * i;
            float* wp = &Wt[kk * 72 + m4A];
            wp[0] = tf32r(ar[i].x); wp[1] = tf32r(ar[i].y);
            wp[2] = tf32r(ar[i].z); wp[3] = tf32r(ar[i].w);
            float* bp = &Bt[kk * 72 + n4B];
            bp[0] = tf32r(br[i].x); bp[1] = tf32r(br[i].y);
            bp[2] = tf32r(br[i].z); bp[3] = tf32r(br[i].w);
        }
        __syncthreads();
        if (kc + 64 < NC) {
            #pragma unroll
            for (int i = 0; i < 4; ++i) {
                int kk = kc + 64 + kkB + 16 * i;
                float4 a4 = make_float4(0.f, 0.f, 0.f, 0.f);
                if (gmA < NH)          a4 = *(const float4*)&a_lo[(size_t)kk * NH + gmA];
                else if (gmA < 2 * NH) a4 = *(const float4*)&a_hi[(size_t)kk * NH + gmA - NH];
                ar[i] = a4;
                br[i] = *(const float4*)&B[(size_t)kk * HW + n0 + n4B];
            }
        }
        #pragma unroll
        for (int ks = 0; ks < 8; ++ks) {
            int k0 = ks * 8;
            uint32_t a0 = __float_as_uint(Wt[(k0 + lk) * 72 + i0w + lrow]);
            uint32_t a1 = __float_as_uint(Wt[(k0 + lk) * 72 + i0w + lrow + 8]);
            uint32_t a2 = __float_as_uint(Wt[(k0 + lk + 4) * 72 + i0w + lrow]);
            uint32_t a3 = __float_as_uint(Wt[(k0 + lk + 4) * 72 + i0w + lrow + 8]);
            #pragma unroll
            for (int np = 0; np < 4; ++np) {
                int ncol = jbase + np * 8 + lrow;
                uint32_t b0 = __float_as_uint(Bt[(k0 + lk) * 72 + ncol]);
                uint32_t b1 = __float_as_uint(Bt[(k0 + lk + 4) * 72 + ncol]);
                mma_tf32(sf[np], a0, a1, a2, a3, b0, b1);
            }
        }
        __syncthreads();
    }

    const int cc0 = 2 * lk;
    #pragma unroll
    for (int rr = 0; rr < 2; ++rr) {
        int gm = m0 + i0w + lrow + rr * 8;
        if (gm >= M) continue;
        #pragma unroll
        for (int nt = 0; nt < 4; ++nt) {
            size_t idx = (size_t)gm * HW + n0 + jbase + nt * 8 + cc0;
            *(float2*)&C[idx] = make_float2(sf[nt][rr * 2 + 0], sf[nt][rr * 2 + 1]);
        }
    }
}

// ---------------- expnorm: single-store softmax over 80 rows ------------------
__global__ void expnorm(const float* __restrict__ AB, float* __restrict__ PAB)
{
    int gid = blockIdx.x * blockDim.x + threadIdx.x;
    if (gid >= 2 * HW) return;
    int h = (gid >= HW) ? 1 : 0;
    int i = gid - h * HW;
    const float* src = AB  + (size_t)h * NH * HW;
    float*       dst = PAB + (size_t)h * NH * HW;
    float s = 0.f;
    #pragma unroll 8
    for (int t = 0; t < NH; ++t) s += __expf(src[t * HW + i]);
    float inv = 1.f / s;
    #pragma unroll 8
    for (int t = 0; t < NH; ++t)
        dst[t * HW + i] = __expf(src[t * HW + i]) * inv;
}

// ---------------- W3 = [w3@efh | w3@efw]  ([256][160], m-major) --------------
__global__ void __launch_bounds__(192) w3eff_kernel(
    const float* __restrict__ w3, const float* __restrict__ efh,
    const float* __restrict__ efw, float* __restrict__ W)
{
    __shared__ float sw3[NC];
    const int m = blockIdx.x;
    const int t = threadIdx.x;
    if (t < NC) sw3[t] = w3[(size_t)m * NC + t];
    __syncthreads();
    if (t >= 2 * NH) return;
    const float* ef = (t < NH) ? (efh + t) : (efw + t - NH);
    float sum = 0.f;
    #pragma unroll 16
    for (int c = 0; c < NC; ++c)
        sum += sw3[c] * ef[(size_t)c * NH];
    W[(size_t)m * 160 + t] = sum;
}

// ---------------- fused final (prefetched, dual source) ----------------------
__global__ void __launch_bounds__(256) final_gemm(
    const float* __restrict__ w2, const float* __restrict__ o1,
    const float* __restrict__ g2, const float* __restrict__ b2,
    const float* __restrict__ m2, const float* __restrict__ v2,
    const float* __restrict__ W3, const float* __restrict__ PAB,
    const float* __restrict__ g3, const float* __restrict__ b3,
    const float* __restrict__ m3, const float* __restrict__ v3,
    const float* __restrict__ x, float* __restrict__ out)
{
    __shared__ float Wt[64 * 72];
    __shared__ float Bt[64 * 72];
    const int tid = threadIdx.x;
    const int wid = tid >> 5, lane = tid & 31;
    const int m0 = blockIdx.y * 64, n0 = blockIdx.x * 64;
    const int i0w = (wid & 3) * 16;
    const int jbase = (wid >> 2) * 32;
    const int lrow = lane >> 2, lk = lane & 3;
    const int mA = tid >> 2, kqA = (tid & 3) << 2;
    const int kkB = tid >> 4, n4B = (tid & 15) << 2;

    float keep[4][4];
    float sf[4][4];
    #pragma unroll
    for (int nt = 0; nt < 4; ++nt)
        #pragma unroll
        for (int e = 0; e < 4; ++e) sf[nt][e] = 0.f;

    float4 ar[4], br[4];
    #pragma unroll
    for (int i = 0; i < 4; ++i) {
        ar[i] = *(const float4*)&w2[(size_t)(m0 + mA) * NC + kqA + 16 * i];
        br[i] = *(const float4*)&o1[(size_t)(kkB + 16 * i) * HW + n0 + n4B];
    }

    #pragma unroll
    for (int src = 0; src < 2; ++src) {
        const int Kp = src ? 160 : NC;
        for (int kc = 0; kc < Kp; kc += 64) {
            const int ck = (Kp - kc < 64) ? (Kp - kc) : 64;
            #pragma unroll
            for (int i = 0; i < 4; ++i) {
                int k4 = kqA + 16 * i;
                if (k4 < ck) {
                    Wt[(k4 + 0) * 72 + mA] = tf32r(ar[i].x);
                    Wt[(k4 + 1) * 72 + mA] = tf32r(ar[i].y);
                    Wt[(k4 + 2) * 72 + mA] = tf32r(ar[i].z);
                    Wt[(k4 + 3) * 72 + mA] = tf32r(ar[i].w);
                }
                int kk = kkB + 16 * i;
                if (kk < ck) {
                    float* bp = &Bt[kk * 72 + n4B];
                    bp[0] = tf32r(br[i].x); bp[1] = tf32r(br[i].y);
                    bp[2] = tf32r(br[i].z); bp[3] = tf32r(br[i].w);
                }
            }
            __syncthreads();
            {
                int srcN = src, kcN = kc + 64;
                if (kcN >= Kp) { srcN = src + 1; kcN = 0; }
                if (srcN < 2) {
                    const float* ApN = srcN ? W3 : w2;
                    const float* BpN = srcN ? PAB : o1;
                    int KpN = srcN ? 160 : NC;
                    int ckN = (KpN - kcN < 64) ? (KpN - kcN) : 64;
                    #pragma unroll
                    for (int i = 0; i < 4; ++i) {
                        int k4 = kqA + 16 * i;
                        if (k4 < ckN)
                            ar[i] = *(const float4*)&ApN[(size_t)(m0 + mA) * KpN + kcN + k4];
                        int kk = kkB + 16 * i;
                        if (kk < ckN)
                            br[i] = *(const float4*)&BpN[(size_t)(kcN + kk) * HW + n0 + n4B];
                    }
                }
            }
            const int nks = ck >> 3;
            for (int ks = 0; ks < nks; ++ks) {
                int k0 = ks * 8;
                uint32_t a0 = __float_as_uint(Wt[(k0 + lk) * 72 + i0w + lrow]);
                uint32_t a1 = __float_as_uint(Wt[(k0 + lk) * 72 + i0w + lrow + 8]);
                uint32_t a2 = __float_as_uint(Wt[(k0 + lk + 4) * 72 + i0w + lrow]);
                uint32_t a3 = __float_as_uint(Wt[(k0 + lk + 4) * 72 + i0w + lrow + 8]);
                #pragma unroll
                for (int np = 0; np < 4; ++np) {
                    int ncol = jbase + np * 8 + lrow;
                    uint32_t b0 = __float_as_uint(Bt[(k0 + lk) * 72 + ncol]);
                    uint32_t b1 = __float_as_uint(Bt[(k0 + lk + 4) * 72 + ncol]);
                    mma_tf32(sf[np], a0, a1, a2, a3, b0, b1);
                }
            }
            __syncthreads();
        }
        const float* gg  = src ? g3 : g2;
        const float* bbp = src ? b3 : b2;
        const float* mmp = src ? m3 : m2;
        const float* vvp = src ? v3 : v2;
        #pragma unroll
        for (int rr = 0; rr < 2; ++rr) {
            int gm = m0 + i0w + lrow + rr * 8;
            float sc = gg[gm] * rsqrtf(vvp[gm] + EPS);
            float sh = bbp[gm] - mmp[gm] * sc;
            #pragma unroll
            for (int nt = 0; nt < 4; ++nt) {
                #pragma unroll
                for (int e2 = 0; e2 < 2; ++e2) {
                    float val = sf[nt][rr * 2 + e2] * sc + sh;
                    val = val / (1.f + __expf(-val));
                    if (src == 0) { keep[nt][rr * 2 + e2] = val; sf[nt][rr * 2 + e2] = 0.f; }
                    else          { keep[nt][rr * 2 + e2] += val; }
                }
            }
        }
    }

    const int cc0 = 2 * lk;
    #pragma unroll
    for (int rr = 0; rr < 2; ++rr) {
        int gm = m0 + i0w + lrow + rr * 8;
        #pragma unroll
        for (int nt = 0; nt < 4; ++nt) {
            size_t idx = (size_t)gm * HW + n0 + jbase + nt * 8 + cc0;
            float2 x2 = *(const float2*)&x[idx];
            *(float2*)&out[idx] = make_float2(keep[nt][rr * 2 + 0] + x2.x,
                                              keep[nt][rr * 2 + 1] + x2.y);
        }
    }
}

// ---------------- branch-1 flash attention: 4 fat warps, occ 3, no Q-hoist ---
#define QS_OFF   0               // bf16 [128][72]
#define KS_OFF   18432           // bf16 [128][72]
#define VS_OFF   36864           // f16  [128][72]
#define RB_OFF   55296           // f16  [64][72] fused Rw+Rh bias
#define FL_SM_BYTES 64512

__global__ void __launch_bounds__(128, 3) flash_kernel(
    const __nv_bfloat16* __restrict__ q, const __nv_bfloat16* __restrict__ k,
    const __half* __restrict__ v, const float* __restrict__ Rh,
    const float* __restrict__ Rw, float* __restrict__ op,
    float* __restrict__ mp, float* __restrict__ lp)
{
    extern __shared__ char smc[];
    __half* RbH = (__half*)(smc + RB_OFF);

    const int tid  = threadIdx.x;
    const int wid  = tid >> 5, lane = tid & 31;
    const int lr   = lane & 7, gq = lane >> 3;
    const int lrowq = lane >> 2, lk = lane & 3;
    const int i0   = blockIdx.x * 64;
    const int spl  = blockIdx.y;
    const int t0   = (spl * 100) / SPLIT;
    const int t1   = ((spl + 1) * 100) / SPLIT;
    const int i0w  = wid * 16;
    const float L2E = 1.4426950408889634f;

    const uint32_t qsb = (uint32_t)__cvta_generic_to_shared(smc + QS_OFF);
    const uint32_t ksb = (uint32_t)__cvta_generic_to_shared(smc + KS_OFF);
    const uint32_t vsb = (uint32_t)__cvta_generic_to_shared(smc + VS_OFF);

    // prologue: Q, K(t0), V(t0) via cp.async (3 groups)
    {
        #pragma unroll
        for (int it = 0; it < 8; ++it) {
            int ch = tid + it * 128;
            int c = ch >> 3, j8 = (ch & 7) * 8;
            cpa16(qsb + (uint32_t)((c * 72 + j8) * 2), &q[(size_t)c * HW + i0 + j8]);
        }
        CPA_COMMIT();
        int j0n = t0 * 64;
        #pragma unroll
        for (int it = 0; it < 8; ++it) {
            int ch = tid + it * 128;
            int c = ch >> 3, j8 = (ch & 7) * 8;
            cpa16(ksb + (uint32_t)((c * 72 + j8) * 2), &k[(size_t)c * HW + j0n + j8]);
        }
        CPA_COMMIT();
        #pragma unroll
        for (int it = 0; it < 8; ++it) {
            int ch = tid + it * 128;
            int c = ch >> 3, j8 = (ch & 7) * 8;
            cpa16(vsb + (uint32_t)((c * 72 + j8) * 2), &v[(size_t)c * HW + j0n + j8]);
        }
        CPA_COMMIT();
    }
    // NOTE: no separate Q wait; the first in-loop wait_group 1 guarantees
    // Q and K groups complete (commit order Q,K,V), published by sync A.

    float d[16][4];
    #pragma unroll
    for (int nt = 0; nt < 16; ++nt)
        #pragma unroll
        for (int e = 0; e < 4; ++e) d[nt][e] = 0.f;
    float m0v = -1e30f, m1v = -1e30f, l0v = 0.f, l1v = 0.f;
    const int r0 = i0w + lrowq, r1 = r0 + 8;

    for (int t = t0; t < t1; ++t) {
        const int j0 = t * 64;
        const bool more = (t + 1 < t1);

        // stage fused bias tile fp16 (safe: previous softmax done at sync C)
        #pragma unroll
        for (int e = 0; e < 8; ++e) {
            int ee = tid + e * 128;
            int row = ee >> 4, c4 = (ee & 15) << 2;
            int gi = i0 + row;
            float4 a = *(const float4*)&Rw[(gi % 80) * HW + j0 + c4];
            float4 b = *(const float4*)&Rh[(gi / 80) * HW + j0 + c4];
            __half2* dst = (__half2*)&RbH[row * 72 + c4];
            dst[0] = __floats2half2_rn(a.x + b.x, a.y + b.y);
            dst[1] = __floats2half2_rn(a.z + b.z, a.w + b.w);
        }
        asm volatile("cp.async.wait_group 1;");   // K(t) landed (Q too, first iter)
        __syncthreads();                          // A: Q/K + bias visible

        // ---- QK^T (bf16), full 64 j per warp; Q frags loaded per k-step ----
        float sf[8][4];
        #pragma unroll
        for (int nb = 0; nb < 8; ++nb)
            #pragma unroll
            for (int e = 0; e < 4; ++e) sf[nb][e] = 0.f;

        #pragma unroll
        for (int ks = 0; ks < 8; ++ks) {
            uint32_t qa0, qa1, qa2, qa3;
            ldsm4t(qa0, qa1, qa2, qa3,
                   qsb + (uint32_t)(((ks * 16 + lr + (gq >> 1) * 8) * 72
                                    + i0w + (gq & 1) * 8) * 2));
            #pragma unroll
            for (int jn = 0; jn < 4; ++jn) {
                uint32_t b0, b1, b2, b3;
                ldsm4t(b0, b1, b2, b3,
                       ksb + (uint32_t)(((ks * 16 + lr + (gq & 1) * 8) * 72
                                        + jn * 16 + (gq >> 1) * 8) * 2));
                mma_bf16(sf[jn * 2],     qa0, qa1, qa2, qa3, b0, b1);
                mma_bf16(sf[jn * 2 + 1], qa0, qa1, qa2, qa3, b2, b3);
            }
        }
        asm volatile("cp.async.wait_group 0;");   // V(t) landed
        __syncthreads();                          // B: Ks free, Vs visible

        if (more) {                               // K(t+1) in place
            int j0n = (t + 1) * 64;
            #pragma unroll
            for (int it = 0; it < 8; ++it) {
                int ch = tid + it * 128;
                int c = ch >> 3, j8 = (ch & 7) * 8;
                cpa16(ksb + (uint32_t)((c * 72 + j8) * 2), &k[(size_t)c * HW + j0n + j8]);
            }
            CPA_COMMIT();
        }

        // ---- softmax entirely warp-local (regs + quad shfl) ----
        #pragma unroll
        for (int nb = 0; nb < 8; ++nb) {
            int col = nb * 8 + 2 * lk;
            float2 b0 = __half22float2(*(__half2*)&RbH[r0 * 72 + col]);
            float2 b1 = __half22float2(*(__half2*)&RbH[r1 * 72 + col]);
            sf[nb][0] += b0.x; sf[nb][1] += b0.y;
            sf[nb][2] += b1.x; sf[nb][3] += b1.y;
        }
        float mx0 = -1e30f, mx1 = -1e30f;
        #pragma unroll
        for (int nb = 0; nb < 8; ++nb) {
            mx0 = fmaxf(mx0, fmaxf(sf[nb][0], sf[nb][1]));
            mx1 = fmaxf(mx1, fmaxf(sf[nb][2], sf[nb][3]));
        }
        mx0 = fmaxf(mx0, __shfl_xor_sync(0xffffffffu, mx0, 1));
        mx0 = fmaxf(mx0, __shfl_xor_sync(0xffffffffu, mx0, 2));
        mx1 = fmaxf(mx1, __shfl_xor_sync(0xffffffffu, mx1, 1));
        mx1 = fmaxf(mx1, __shfl_xor_sync(0xffffffffu, mx1, 2));
        float nm0 = fmaxf(m0v, mx0), nm1 = fmaxf(m1v, mx1);
        float f0 = exp2f((m0v - nm0) * L2E);
        float f1 = exp2f((m1v - nm1) * L2E);
        uint32_t ph[8][2];
        float s0 = 0.f, s1 = 0.f;
        #pragma unroll
        for (int nb = 0; nb < 8; ++nb) {
            float u0 = (sf[nb][0] - nm0) * L2E, u1 = (sf[nb][1] - nm0) * L2E;
            float u2 = (sf[nb][2] - nm1) * L2E, u3 = (sf[nb][3] - nm1) * L2E;
            uint32_t p0, p1;
            asm("cvt.rn.f16x2.f32 %0, %1, %2;" : "=r"(p0) : "f"(u1), "f"(u0));
            asm("ex2.approx.f16x2 %0, %0;" : "+r"(p0));
            asm("cvt.rn.f16x2.f32 %0, %1, %2;" : "=r"(p1) : "f"(u3), "f"(u2));
            asm("ex2.approx.f16x2 %0, %0;" : "+r"(p1));
            ph[nb][0] = p0; ph[nb][1] = p1;
            float2 e0 = __half22float2(*reinterpret_cast<__half2*>(&p0));
            float2 e1 = __half22float2(*reinterpret_cast<__half2*>(&p1));
            s0 += e0.x + e0.y;
            s1 += e1.x + e1.y;
        }
        s0 += __shfl_xor_sync(0xffffffffu, s0, 1);
        s0 += __shfl_xor_sync(0xffffffffu, s0, 2);
        s1 += __shfl_xor_sync(0xffffffffu, s1, 1);
        s1 += __shfl_xor_sync(0xffffffffu, s1, 2);
        l0v = l0v * f0 + s0;  m0v = nm0;
        l1v = l1v * f1 + s1;  m1v = nm1;
        #pragma unroll
        for (int nt = 0; nt < 16; ++nt) {
            d[nt][0] *= f0; d[nt][1] *= f0;
            d[nt][2] *= f1; d[nt][3] *= f1;
        }

        // ---- P @ V^T (fp16): A = register P frags, k = 64 j, n = 128 c ----
        #pragma unroll
        for (int ks = 0; ks < 4; ++ks) {
            uint32_t a0 = ph[2 * ks][0], a1 = ph[2 * ks][1];
            uint32_t a2 = ph[2 * ks + 1][0], a3 = ph[2 * ks + 1][1];
            #pragma unroll
            for (int np = 0; np < 8; ++np) {
                uint32_t b0, b1, b2, b3;
                ldsm4(b0, b1, b2, b3,
                      vsb + (uint32_t)(((np * 16 + lr + (gq >> 1) * 8) * 72
                                       + ks * 16 + (gq & 1) * 8) * 2));
                mma_f16(d[np * 2],     a0, a1, a2, a3, b0, b1);
                mma_f16(d[np * 2 + 1], a0, a1, a2, a3, b2, b3);
            }
        }
        __syncthreads();                          // C: Vs free, bias free

        if (more) {                               // V(t+1)
            int j0n = (t + 1) * 64;
            #pragma unroll
            for (int it = 0; it < 8; ++it) {
                int ch = tid + it * 128;
                int c = ch >> 3, j8 = (ch & 7) * 8;
                cpa16(vsb + (uint32_t)((c * 72 + j8) * 2), &v[(size_t)c * HW + j0n + j8]);
            }
            CPA_COMMIT();
        }
    }

    // ---- epilogue: warp owns 16 rows x all 128 channels; direct writes ----
    #pragma unroll
    for (int nt = 0; nt < 16; ++nt) {
        int c = nt * 8 + 2 * lk;
        op[(size_t)(spl * NC + c)     * HW + i0 + r0] = d[nt][0];
        op[(size_t)(spl * NC + c + 1) * HW + i0 + r0] = d[nt][1];
        op[(size_t)(spl * NC + c)     * HW + i0 + r1] = d[nt][2];
        op[(size_t)(spl * NC + c + 1) * HW + i0 + r1] = d[nt][3];
    }
    if (lk == 0) {
        mp[spl * HW + i0 + r0] = m0v;
        mp[spl * HW + i0 + r1] = m1v;
        lp[spl * HW + i0 + r0] = l0v;
        lp[spl * HW + i0 + r1] = l1v;
    }
}

// ---------------- split-j combine (channel-parallel) -------------------------
__global__ void combine_kernel(const float* __restrict__ op,
                               const float* __restrict__ mp,
                               const float* __restrict__ lp,
                               float* __restrict__ out1)
{
    int i = blockIdx.x * blockDim.x + threadIdx.x;
    if (i >= HW) return;
    int c0 = blockIdx.y * 8;
    float m[SPLIT], w[SPLIT];
    float M = -1e30f;
    #pragma unroll
    for (int s = 0; s < SPLIT; ++s) { m[s] = mp[s * HW + i]; M = fmaxf(M, m[s]); }
    float L = 0.f;
    #pragma unroll
    for (int s = 0; s < SPLIT; ++s) { w[s] = __expf(m[s] - M); L += lp[s * HW + i] * w[s]; }
    float inv = 1.f / L;
    for (int c = c0; c < c0 + 8; ++c) {
        float acc = 0.f;
        #pragma unroll
        for (int s = 0; s < SPLIT; ++s)
            acc += op[((size_t)(s * NC + c)) * HW + i] * w[s];
        out1[(size_t)c * HW + i] = acc * inv;
    }
}

// -------------------------------- launch -------------------------------------
extern "C" void kernel_launch(void* const* d_in, const int* in_sizes, int n_in,
                              void* d_out, int out_size)
{
    (void)in_sizes; (void)n_in; (void)out_size;
    const float* x    = (const float*)d_in[0];
    const float* w1   = (const float*)d_in[1];
    const float* g1   = (const float*)d_in[2];
    const float* b1   = (const float*)d_in[3];
    const float* m1   = (const float*)d_in[4];
    const float* v1   = (const float*)d_in[5];
    const float* w2   = (const float*)d_in[6];
    const float* g2   = (const float*)d_in[7];
    const float* b2   = (const float*)d_in[8];
    const float* m2   = (const float*)d_in[9];
    const float* v2   = (const float*)d_in[10];
    const float* w3   = (const float*)d_in[11];
    const float* g3   = (const float*)d_in[12];
    const float* b3   = (const float*)d_in[13];
    const float* m3   = (const float*)d_in[14];
    const float* v3   = (const float*)d_in[15];
    const float* wq   = (const float*)d_in[16];
    const float* bq   = (const float*)d_in[17];
    const float* wk   = (const float*)d_in[18];
    const float* bk   = (const float*)d_in[19];
    const float* wv   = (const float*)d_in[20];
    const float* bv   = (const float*)d_in[21];
    const float* wp   = (const float*)d_in[22];
    const float* bp   = (const float*)d_in[23];
    const float* relh = (const float*)d_in[24];
    const float* relw = (const float*)d_in[25];
    const float* efh  = (const float*)d_in[26];
    const float* efw  = (const float*)d_in[27];
    float* out = (float*)d_out;

    float *px1, *pq, *pp, *pRW, *pAB, *pPAB, *pW3, *po1, *pop, *pmp, *plp;
    __nv_bfloat16 *pqb, *pkb;
    __half *pvh;
    cudaGetSymbolAddress((void**)&px1, d_x1);
    cudaGetSymbolAddress((void**)&pq,  d_q);
    cudaGetSymbolAddress((void**)&pp,  d_p);
    cudaGetSymbolAddress((void**)&pqb, d_qb);
    cudaGetSymbolAddress((void**)&pkb, d_kb);
    cudaGetSymbolAddress((void**)&pvh, d_vh);
    cudaGetSymbolAddress((void**)&pRW, d_RW);
    cudaGetSymbolAddress((void**)&pAB, d_AB);
    cudaGetSymbolAddress((void**)&pPAB, d_PAB);
    cudaGetSymbolAddress((void**)&pW3, d_W3);
    cudaGetSymbolAddress((void**)&po1, d_o1);
    cudaGetSymbolAddress((void**)&pop, d_op);
    cudaGetSymbolAddress((void**)&pmp, d_mp);
    cudaGetSymbolAddress((void**)&plp, d_lp);

    cudaFuncSetAttribute(flash_kernel,
        cudaFuncAttributeMaxDynamicSharedMemorySize, FL_SM_BYTES);

    dim3 g100_2(100, 2), g100_4(100, 4);
    dim3 gproj(100, 2, 4), gkr(100, 3, 2), gfl(100, SPLIT), gcmb(25, 16);

    // [0] W3 = [w3@efh | w3@efw]
    w3eff_kernel<<<ND, 192>>>(w3, efh, efw, pW3);
    // [1] x1 = SiLU(BN(w1 @ x))
    tgemm<2><<<g100_2, 256>>>(w1, x, px1, NC, ND, g1, b1, m1, v1);
    // [2] fused q/k/v/p projections (fp32 q,p; bf16 q,k; fp16 v)
    proj4<<<gproj, 256>>>(px1, wq, bq, wk, bk, wv, bv, wp, bp,
        pq, pqb, pkb, pvh, pp);
    // [3] z=0: [Rh;Rw] = [rel_h;rel_w]^T q;  z=1: [ABh;ABw] = [ef_h;ef_w]^T p
    krgemm<<<gkr, 256>>>(relh, relw, pq, pRW, efh, efw, pp, pAB);
    // [4] PAB = per-column softmax of both halves (single-store)
    expnorm<<<50, 256>>>(pAB, pPAB);
    // [5] flash attention (4 fat warps, occ 3, Q re-ldsm per tile)
    flash_kernel<<<gfl, 128, FL_SM_BYTES>>>(pqb, pkb, pvh,
        pRW, pRW + NH * HW, pop, pmp, plp);
    // [6] combine split partials -> out1
    combine_kernel<<<gcmb, 256>>>(pop, pmp, plp, po1);
    // [7] out = x + SiLU(BN2(w2@o1)) + SiLU(BN3(W3@PAB))
    final_gemm<<<g100_4, 256>>>(w2, po1, g2, b2, m2, v2,
        pW3, pPAB, g3, b3, m3, v3, x, out);
}